// round 1
// baseline (speedup 1.0000x reference)
#include <cuda_runtime.h>
#include <math.h>

namespace {

constexpr int N = 50000;
constexpr int E = 800000;
constexpr float AVG_D_LOG = 2.8332f;
constexpr float EPS_STD = 1e-5f;
constexpr float EPS_BN = 1e-5f;
constexpr float FLT_BIG = 3.402823466e+38f;

// ---- scratch (device globals: allocation-free contract) ----
__device__ int g_deg[N];
__device__ int g_offs[N + 1];
__device__ int g_cursor[N];
__device__ int g_perm[E];
__device__ __align__(16) float g_msgh[(size_t)E * 64];   // messages in SORTED (CSR) order
__device__ __align__(16) float g_msgp[(size_t)E * 64];
__device__ __align__(16) float g_aggh[(size_t)N * 768];
__device__ __align__(16) float g_aggp[(size_t)N * 768];
__device__ float g_bnsum[64];
__device__ float g_bnsq[64];

// ---------------- init ----------------
__global__ void k_init() {
    int i = blockIdx.x * blockDim.x + threadIdx.x;
    if (i < N) g_deg[i] = 0;
    if (i < 64) { g_bnsum[i] = 0.f; g_bnsq[i] = 0.f; }
}

// ---------------- degree histogram ----------------
__global__ void k_hist(const int* __restrict__ dst) {
    int e = blockIdx.x * blockDim.x + threadIdx.x;
    if (e < E) atomicAdd(&g_deg[dst[e]], 1);
}

// ---------------- exclusive scan (single block) ----------------
__global__ void k_scan() {
    __shared__ int s[1024];
    int t = threadIdx.x;
    int carry = 0;
    for (int base = 0; base < N; base += 1024) {
        int v = (base + t < N) ? g_deg[base + t] : 0;
        s[t] = v;
        __syncthreads();
        for (int off = 1; off < 1024; off <<= 1) {
            int add = (t >= off) ? s[t - off] : 0;
            __syncthreads();
            s[t] += add;
            __syncthreads();
        }
        int incl = s[t];
        if (base + t < N) {
            int ex = carry + incl - v;
            g_offs[base + t] = ex;
            g_cursor[base + t] = ex;
        }
        carry += s[1023];
        __syncthreads();
    }
    if (t == 0) g_offs[N] = carry;
}

// ---------------- scatter: build permutation (counting sort by dst) ----------------
__global__ void k_scatter(const int* __restrict__ dst) {
    int e = blockIdx.x * blockDim.x + threadIdx.x;
    if (e < E) {
        int pos = atomicAdd(&g_cursor[dst[e]], 1);
        g_perm[pos] = e;
    }
}

// ---------------- edge GEMM: msg_h = [h_src,h_dst,e] @ W_pre_h + b ; msg_p likewise ---
// 128 edges x 64 outs per block, BK=32, 256 threads, 8x4 micro-tile.
__global__ void __launch_bounds__(256) k_edgegemm(
    const float* __restrict__ h, const float* __restrict__ p,
    const float* __restrict__ ef,
    const int* __restrict__ src, const int* __restrict__ dst,
    const float* __restrict__ Wh, const float* __restrict__ bh,
    const float* __restrict__ Wp, const float* __restrict__ bp)
{
    __shared__ __align__(16) float Xs[128 * 33];
    __shared__ __align__(16) float Ws[32 * 64];
    __shared__ int s_src[128], s_dst[128], s_eid[128];

    int tid = threadIdx.x;
    int base = blockIdx.x * 128;           // sorted position base

    for (int j = tid; j < 128; j += 256) {
        int eid = g_perm[base + j];
        s_eid[j] = eid;
        s_src[j] = src[eid];
        s_dst[j] = dst[eid];
    }
    __syncthreads();

    int tx = tid & 15;          // out group: outs [4tx, 4tx+4)
    int te = tid >> 4;          // edge group: edges [8te, 8te+8)
    int le = tid >> 1;          // loader edge 0..127
    int lh = (tid & 1) * 16;    // loader k offset

    int wkk = tid >> 3;         // W loader row 0..31
    int woc = (tid & 7) * 8;    // W loader col 0..56

    float acc[8][4];

    // ============ phase H (K=288, 9 tiles) ============
#pragma unroll
    for (int i = 0; i < 8; i++)
#pragma unroll
        for (int j = 0; j < 4; j++) acc[i][j] = 0.f;

    for (int t = 0; t < 9; t++) {
        int k0 = t * 32;
        const float* rowp;
        if (t < 4)      rowp = h + (size_t)s_src[le] * 128 + k0;
        else if (t < 8) rowp = h + (size_t)s_dst[le] * 128 + (k0 - 128);
        else            rowp = ef + (size_t)s_eid[le] * 32;
#pragma unroll
        for (int j = 0; j < 16; j++) Xs[le * 33 + lh + j] = rowp[lh + j];
        const float* wrow = Wh + (size_t)(k0 + wkk) * 64 + woc;
#pragma unroll
        for (int j = 0; j < 8; j++) Ws[wkk * 64 + woc + j] = wrow[j];
        __syncthreads();
#pragma unroll
        for (int kk = 0; kk < 32; kk++) {
            float4 w = *(const float4*)&Ws[kk * 64 + tx * 4];
#pragma unroll
            for (int i = 0; i < 8; i++) {
                float x = Xs[(te * 8 + i) * 33 + kk];
                acc[i][0] += x * w.x; acc[i][1] += x * w.y;
                acc[i][2] += x * w.z; acc[i][3] += x * w.w;
            }
        }
        __syncthreads();
    }
    {
        float4 bias = *(const float4*)&bh[tx * 4];
#pragma unroll
        for (int i = 0; i < 8; i++) {
            int pos = base + te * 8 + i;
            float4 v = make_float4(acc[i][0] + bias.x, acc[i][1] + bias.y,
                                   acc[i][2] + bias.z, acc[i][3] + bias.w);
            *(float4*)&g_msgh[(size_t)pos * 64 + tx * 4] = v;
        }
    }

    // ============ phase P (K=160, 5 tiles) ============
#pragma unroll
    for (int i = 0; i < 8; i++)
#pragma unroll
        for (int j = 0; j < 4; j++) acc[i][j] = 0.f;

    for (int t = 0; t < 5; t++) {
        int k0 = t * 32;
        const float* rowp;
        if (t < 2)      rowp = p + (size_t)s_src[le] * 64 + k0;
        else if (t < 4) rowp = p + (size_t)s_dst[le] * 64 + (k0 - 64);
        else            rowp = ef + (size_t)s_eid[le] * 32;
#pragma unroll
        for (int j = 0; j < 16; j++) Xs[le * 33 + lh + j] = rowp[lh + j];
        const float* wrow = Wp + (size_t)(k0 + wkk) * 64 + woc;
#pragma unroll
        for (int j = 0; j < 8; j++) Ws[wkk * 64 + woc + j] = wrow[j];
        __syncthreads();
#pragma unroll
        for (int kk = 0; kk < 32; kk++) {
            float4 w = *(const float4*)&Ws[kk * 64 + tx * 4];
#pragma unroll
            for (int i = 0; i < 8; i++) {
                float x = Xs[(te * 8 + i) * 33 + kk];
                acc[i][0] += x * w.x; acc[i][1] += x * w.y;
                acc[i][2] += x * w.z; acc[i][3] += x * w.w;
            }
        }
        __syncthreads();
    }
    {
        float4 bias = *(const float4*)&bp[tx * 4];
#pragma unroll
        for (int i = 0; i < 8; i++) {
            int pos = base + te * 8 + i;
            float4 v = make_float4(acc[i][0] + bias.x, acc[i][1] + bias.y,
                                   acc[i][2] + bias.z, acc[i][3] + bias.w);
            *(float4*)&g_msgp[(size_t)pos * 64 + tx * 4] = v;
        }
    }
}

// ---------------- per-node PNA aggregation (warp per node, CSR segments) -------------
__global__ void k_agg() {
    int warp = (blockIdx.x * blockDim.x + threadIdx.x) >> 5;
    int l = threadIdx.x & 31;
    if (warp >= N) return;
    int n = warp;
    int s0 = g_offs[n];
    int s1 = g_offs[n + 1];
    int d = s1 - s0;

    float sm[4] = {0.f, 0.f, 0.f, 0.f};
    float sq[4] = {0.f, 0.f, 0.f, 0.f};
    float mx[4] = {-FLT_BIG, -FLT_BIG, -FLT_BIG, -FLT_BIG};
    float mn[4] = {FLT_BIG, FLT_BIG, FLT_BIG, FLT_BIG};

    for (int i = s0; i < s1; i++) {
        const float* rh = g_msgh + (size_t)i * 64;
        const float* rp = g_msgp + (size_t)i * 64;
        float v0 = rh[l];
        float v1 = rh[l + 32];
        float v2 = rp[l];
        float v3 = rp[l + 32];
        sm[0] += v0; sq[0] += v0 * v0; mx[0] = fmaxf(mx[0], v0); mn[0] = fminf(mn[0], v0);
        sm[1] += v1; sq[1] += v1 * v1; mx[1] = fmaxf(mx[1], v1); mn[1] = fminf(mn[1], v1);
        sm[2] += v2; sq[2] += v2 * v2; mx[2] = fmaxf(mx[2], v2); mn[2] = fminf(mn[2], v2);
        sm[3] += v3; sq[3] += v3 * v3; mx[3] = fmaxf(mx[3], v3); mn[3] = fminf(mn[3], v3);
    }

    float degc = fmaxf((float)d, 1.f);
    float inv = 1.f / degc;
    bool has = d > 0;
    float logd = has ? logf((float)d + 1.f) : 1.f;
    float amp = logd / AVG_D_LOG;
    float att = AVG_D_LOG / logd;

    float* outh = g_aggh + (size_t)n * 768;
    float* outp = g_aggp + (size_t)n * 768;

#pragma unroll
    for (int c = 0; c < 4; c++) {
        float mean = sm[c] * inv;
        float var = fmaxf(sq[c] * inv - mean * mean, 0.f);
        float sd = sqrtf(var + EPS_STD);
        float MX = has ? mx[c] : 0.f;
        float MN = has ? mn[c] : 0.f;
        float* o = (c < 2) ? outh : outp;
        int f = l + ((c & 1) ? 32 : 0);
        o[f] = mean;            o[64 + f] = MX;        o[128 + f] = MN;        o[192 + f] = sd;
        o[256 + f] = mean * amp; o[320 + f] = MX * amp; o[384 + f] = MN * amp; o[448 + f] = sd * amp;
        o[512 + f] = mean * att; o[576 + f] = MX * att; o[640 + f] = MN * att; o[704 + f] = sd * att;
    }
}

// ---------------- node GEMMs: h_out = [h, agg_h]@W_post_h + b ; p likewise ----------
__global__ void __launch_bounds__(256) k_nodegemm(
    const float* __restrict__ h, const float* __restrict__ p,
    const float* __restrict__ snorm,
    const float* __restrict__ Woh, const float* __restrict__ boh,
    const float* __restrict__ Wop, const float* __restrict__ bop,
    float* __restrict__ out)
{
    __shared__ __align__(16) float Xs[128 * 33];
    __shared__ __align__(16) float Ws[32 * 64];

    int tid = threadIdx.x;
    int base = blockIdx.x * 128;

    int tx = tid & 15;
    int te = tid >> 4;
    int le = tid >> 1;
    int lh = (tid & 1) * 16;
    int wkk = tid >> 3;
    int woc = (tid & 7) * 8;

    int nl = base + le;
    bool okl = nl < N;

    float acc[8][4];

    // ============ phase H (K=896, 28 tiles) ============
#pragma unroll
    for (int i = 0; i < 8; i++)
#pragma unroll
        for (int j = 0; j < 4; j++) acc[i][j] = 0.f;

    for (int t = 0; t < 28; t++) {
        int k0 = t * 32;
        const float* rowp = (t < 4) ? (h + (size_t)nl * 128 + k0)
                                    : (g_aggh + (size_t)nl * 768 + (k0 - 128));
#pragma unroll
        for (int j = 0; j < 16; j++) Xs[le * 33 + lh + j] = okl ? rowp[lh + j] : 0.f;
        const float* wrow = Woh + (size_t)(k0 + wkk) * 64 + woc;
#pragma unroll
        for (int j = 0; j < 8; j++) Ws[wkk * 64 + woc + j] = wrow[j];
        __syncthreads();
#pragma unroll
        for (int kk = 0; kk < 32; kk++) {
            float4 w = *(const float4*)&Ws[kk * 64 + tx * 4];
#pragma unroll
            for (int i = 0; i < 8; i++) {
                float x = Xs[(te * 8 + i) * 33 + kk];
                acc[i][0] += x * w.x; acc[i][1] += x * w.y;
                acc[i][2] += x * w.z; acc[i][3] += x * w.w;
            }
        }
        __syncthreads();
    }
    {
        float4 bias = *(const float4*)&boh[tx * 4];
#pragma unroll
        for (int i = 0; i < 8; i++) {
            int n = base + te * 8 + i;
            if (n < N) {
                float sn = snorm[n];
                float4 v = make_float4((acc[i][0] + bias.x) * sn, (acc[i][1] + bias.y) * sn,
                                       (acc[i][2] + bias.z) * sn, (acc[i][3] + bias.w) * sn);
                *(float4*)&out[(size_t)n * 64 + tx * 4] = v;
            }
        }
    }

    // ============ phase P (K=832, 26 tiles) ============
#pragma unroll
    for (int i = 0; i < 8; i++)
#pragma unroll
        for (int j = 0; j < 4; j++) acc[i][j] = 0.f;

    for (int t = 0; t < 26; t++) {
        int k0 = t * 32;
        const float* rowp = (t < 2) ? (p + (size_t)nl * 64 + k0)
                                    : (g_aggp + (size_t)nl * 768 + (k0 - 64));
#pragma unroll
        for (int j = 0; j < 16; j++) Xs[le * 33 + lh + j] = okl ? rowp[lh + j] : 0.f;
        const float* wrow = Wop + (size_t)(k0 + wkk) * 64 + woc;
#pragma unroll
        for (int j = 0; j < 8; j++) Ws[wkk * 64 + woc + j] = wrow[j];
        __syncthreads();
#pragma unroll
        for (int kk = 0; kk < 32; kk++) {
            float4 w = *(const float4*)&Ws[kk * 64 + tx * 4];
#pragma unroll
            for (int i = 0; i < 8; i++) {
                float x = Xs[(te * 8 + i) * 33 + kk];
                acc[i][0] += x * w.x; acc[i][1] += x * w.y;
                acc[i][2] += x * w.z; acc[i][3] += x * w.w;
            }
        }
        __syncthreads();
    }
    {
        float4 bias = *(const float4*)&bop[tx * 4];
        float* outp = out + (size_t)N * 64;
#pragma unroll
        for (int i = 0; i < 8; i++) {
            int n = base + te * 8 + i;
            if (n < N) {
                float4 v = make_float4(acc[i][0] + bias.x, acc[i][1] + bias.y,
                                       acc[i][2] + bias.z, acc[i][3] + bias.w);
                *(float4*)&outp[(size_t)n * 64 + tx * 4] = v;
            }
        }
    }
}

// ---------------- batchnorm stats ----------------
__global__ void k_bnstats(const float* __restrict__ out) {
    __shared__ float ss[4][64];
    __shared__ float sqv[4][64];
    int f = threadIdx.x & 63;
    int rg = threadIdx.x >> 6;
    int r0 = blockIdx.x * 128;
    int rend = r0 + 128;
    if (rend > N) rend = N;
    float s = 0.f, q = 0.f;
    for (int r = r0 + rg; r < rend; r += 4) {
        float x = out[(size_t)r * 64 + f];
        s += x; q += x * x;
    }
    ss[rg][f] = s; sqv[rg][f] = q;
    __syncthreads();
    if (threadIdx.x < 64) {
        float S = ss[0][f] + ss[1][f] + ss[2][f] + ss[3][f];
        float Q = sqv[0][f] + sqv[1][f] + sqv[2][f] + sqv[3][f];
        atomicAdd(&g_bnsum[f], S);
        atomicAdd(&g_bnsq[f], Q);
    }
}

// ---------------- batchnorm apply ----------------
__global__ void k_bnapply(float* __restrict__ out,
                          const float* __restrict__ gamma,
                          const float* __restrict__ beta) {
    int i = blockIdx.x * blockDim.x + threadIdx.x;
    if (i >= N * 64) return;
    int f = i & 63;
    const float invN = 1.f / (float)N;
    float mu = g_bnsum[f] * invN;
    float var = g_bnsq[f] * invN - mu * mu;
    float x = out[i];
    out[i] = (x - mu) * rsqrtf(var + EPS_BN) * gamma[f] + beta[f];
}

} // namespace

extern "C" void kernel_launch(void* const* d_in, const int* in_sizes, int n_in,
                              void* d_out, int out_size) {
    const float* h     = (const float*)d_in[0];
    const float* p     = (const float*)d_in[1];
    const float* e     = (const float*)d_in[2];
    const int*   src   = (const int*)d_in[3];
    const int*   dst   = (const int*)d_in[4];
    const float* snorm = (const float*)d_in[5];
    const float* Wph   = (const float*)d_in[6];
    const float* bph   = (const float*)d_in[7];
    const float* Wpp   = (const float*)d_in[8];
    const float* bpp   = (const float*)d_in[9];
    const float* Woh   = (const float*)d_in[10];
    const float* boh   = (const float*)d_in[11];
    const float* Wop   = (const float*)d_in[12];
    const float* bop   = (const float*)d_in[13];
    const float* gamma = (const float*)d_in[14];
    const float* beta  = (const float*)d_in[15];
    float* out = (float*)d_out;

    k_init<<<(N + 255) / 256, 256>>>();
    k_hist<<<(E + 255) / 256, 256>>>(dst);
    k_scan<<<1, 1024>>>();
    k_scatter<<<(E + 255) / 256, 256>>>(dst);
    k_edgegemm<<<E / 128, 256>>>(h, p, e, src, dst, Wph, bph, Wpp, bpp);
    k_agg<<<(N * 32 + 255) / 256, 256>>>();
    k_nodegemm<<<(N + 127) / 128, 256>>>(h, p, snorm, Woh, boh, Wop, bop, out);
    k_bnstats<<<(N + 127) / 128, 256>>>(out);
    k_bnapply<<<(N * 64 + 255) / 256, 256>>>(out, gamma, beta);
}

// round 2
// speedup vs baseline: 1.2803x; 1.2803x over previous
#include <cuda_runtime.h>
#include <math.h>

namespace {

constexpr int N = 50000;
constexpr int E = 800000;
constexpr float AVG_D_LOG = 2.8332f;
constexpr float EPS_STD = 1e-5f;
constexpr float EPS_BN = 1e-5f;
constexpr float FLT_BIG = 3.402823466e+38f;
constexpr int PITCH = 130;     // k-major Xs pitch (floats)

typedef unsigned long long ull;

__device__ __forceinline__ ull fma2(ull a, ull b, ull c) {
    ull d;
    asm("fma.rn.f32x2 %0,%1,%2,%3;" : "=l"(d) : "l"(a), "l"(b), "l"(c));
    return d;
}
__device__ __forceinline__ ull pack2(float x, float y) {
    ull d;
    asm("mov.b64 %0,{%1,%2};" : "=l"(d) : "f"(x), "f"(y));
    return d;
}
__device__ __forceinline__ float2 unpack2(ull v) {
    float2 r;
    asm("mov.b64 {%0,%1},%2;" : "=f"(r.x), "=f"(r.y) : "l"(v));
    return r;
}

// ---- scratch (device globals: allocation-free contract) ----
__device__ int g_deg[N];
__device__ int g_offs[N + 1];
__device__ int g_cursor[N];
__device__ int g_perm[E];
__device__ __align__(16) float g_msgh[(size_t)E * 64];   // messages in SORTED (CSR) order
__device__ __align__(16) float g_msgp[(size_t)E * 64];
__device__ __align__(16) float g_aggh[(size_t)N * 768];
__device__ __align__(16) float g_aggp[(size_t)N * 768];
__device__ float g_bnsum[64];
__device__ float g_bnsq[64];

// ---------------- init ----------------
__global__ void k_init() {
    int i = blockIdx.x * blockDim.x + threadIdx.x;
    if (i < N) g_deg[i] = 0;
    if (i < 64) { g_bnsum[i] = 0.f; g_bnsq[i] = 0.f; }
}

// ---------------- degree histogram ----------------
__global__ void k_hist(const int* __restrict__ dst) {
    int e = blockIdx.x * blockDim.x + threadIdx.x;
    if (e < E) atomicAdd(&g_deg[dst[e]], 1);
}

// ---------------- exclusive scan (single block) ----------------
__global__ void k_scan() {
    __shared__ int s[1024];
    int t = threadIdx.x;
    int carry = 0;
    for (int base = 0; base < N; base += 1024) {
        int v = (base + t < N) ? g_deg[base + t] : 0;
        s[t] = v;
        __syncthreads();
        for (int off = 1; off < 1024; off <<= 1) {
            int add = (t >= off) ? s[t - off] : 0;
            __syncthreads();
            s[t] += add;
            __syncthreads();
        }
        int incl = s[t];
        if (base + t < N) {
            int ex = carry + incl - v;
            g_offs[base + t] = ex;
            g_cursor[base + t] = ex;
        }
        carry += s[1023];
        __syncthreads();
    }
    if (t == 0) g_offs[N] = carry;
}

// ---------------- scatter: build permutation (counting sort by dst) ----------------
__global__ void k_scatter(const int* __restrict__ dst) {
    int e = blockIdx.x * blockDim.x + threadIdx.x;
    if (e < E) {
        int pos = atomicAdd(&g_cursor[dst[e]], 1);
        g_perm[pos] = e;
    }
}

// ---------------- edge GEMM (f32x2 packed): 128 edges x 64 outs / block ----------
__global__ void __launch_bounds__(256) k_edgegemm(
    const float* __restrict__ h, const float* __restrict__ p,
    const float* __restrict__ ef,
    const int* __restrict__ src, const int* __restrict__ dst,
    const float* __restrict__ Wh, const float* __restrict__ bh,
    const float* __restrict__ Wp, const float* __restrict__ bp)
{
    __shared__ __align__(16) float Xs[32 * PITCH];      // k-major: Xs[k][edge]
    __shared__ __align__(16) float Ws[32 * 64];
    __shared__ int s_src[128], s_dst[128], s_eid[128];

    int tid = threadIdx.x;
    int base = blockIdx.x * 128;           // sorted position base

    for (int j = tid; j < 128; j += 256) {
        int eid = g_perm[base + j];
        s_eid[j] = eid;
        s_src[j] = src[eid];
        s_dst[j] = dst[eid];
    }
    __syncthreads();

    int tx = tid & 15;          // out group: outs [4tx, 4tx+4)
    int te = tid >> 4;          // edge group: edges [8te, 8te+8) = 4 pairs
    int le = tid & 127;         // loader edge
    int lh = (tid >> 7) * 16;   // loader k offset (0 or 16)

    int wkk = tid >> 3;         // W loader row 0..31
    int woc = (tid & 7) * 8;    // W loader col 0..56

    ull acc[4][4];

    // ============ phase H (K=288, 9 tiles) ============
#pragma unroll
    for (int i = 0; i < 4; i++)
#pragma unroll
        for (int j = 0; j < 4; j++) acc[i][j] = 0ull;

    for (int t = 0; t < 9; t++) {
        int k0 = t * 32;
        const float* rowp;
        if (t < 4)      rowp = h + (size_t)s_src[le] * 128 + k0;
        else if (t < 8) rowp = h + (size_t)s_dst[le] * 128 + (k0 - 128);
        else            rowp = ef + (size_t)s_eid[le] * 32;
#pragma unroll
        for (int q = 0; q < 4; q++) {
            float4 a = *(const float4*)(rowp + lh + q * 4);
            Xs[(lh + q * 4 + 0) * PITCH + le] = a.x;
            Xs[(lh + q * 4 + 1) * PITCH + le] = a.y;
            Xs[(lh + q * 4 + 2) * PITCH + le] = a.z;
            Xs[(lh + q * 4 + 3) * PITCH + le] = a.w;
        }
        const float* wrow = Wh + (size_t)(k0 + wkk) * 64 + woc;
        *(float4*)&Ws[wkk * 64 + woc]     = *(const float4*)(wrow);
        *(float4*)&Ws[wkk * 64 + woc + 4] = *(const float4*)(wrow + 4);
        __syncthreads();
#pragma unroll 16
        for (int kk = 0; kk < 32; kk++) {
            float4 w = *(const float4*)&Ws[kk * 64 + tx * 4];
            ull w0 = pack2(w.x, w.x), w1 = pack2(w.y, w.y);
            ull w2 = pack2(w.z, w.z), w3 = pack2(w.w, w.w);
            const ull* xp = (const ull*)&Xs[kk * PITCH + te * 8];
#pragma unroll
            for (int i = 0; i < 4; i++) {
                ull x = xp[i];
                acc[i][0] = fma2(x, w0, acc[i][0]);
                acc[i][1] = fma2(x, w1, acc[i][1]);
                acc[i][2] = fma2(x, w2, acc[i][2]);
                acc[i][3] = fma2(x, w3, acc[i][3]);
            }
        }
        __syncthreads();
    }
    {
        float4 bias = *(const float4*)&bh[tx * 4];
#pragma unroll
        for (int i = 0; i < 4; i++) {
            float2 c0 = unpack2(acc[i][0]), c1 = unpack2(acc[i][1]);
            float2 c2 = unpack2(acc[i][2]), c3 = unpack2(acc[i][3]);
            int pos = base + te * 8 + 2 * i;
            *(float4*)&g_msgh[(size_t)pos * 64 + tx * 4] =
                make_float4(c0.x + bias.x, c1.x + bias.y, c2.x + bias.z, c3.x + bias.w);
            *(float4*)&g_msgh[(size_t)(pos + 1) * 64 + tx * 4] =
                make_float4(c0.y + bias.x, c1.y + bias.y, c2.y + bias.z, c3.y + bias.w);
        }
    }

    // ============ phase P (K=160, 5 tiles) ============
#pragma unroll
    for (int i = 0; i < 4; i++)
#pragma unroll
        for (int j = 0; j < 4; j++) acc[i][j] = 0ull;

    for (int t = 0; t < 5; t++) {
        int k0 = t * 32;
        const float* rowp;
        if (t < 2)      rowp = p + (size_t)s_src[le] * 64 + k0;
        else if (t < 4) rowp = p + (size_t)s_dst[le] * 64 + (k0 - 64);
        else            rowp = ef + (size_t)s_eid[le] * 32;
#pragma unroll
        for (int q = 0; q < 4; q++) {
            float4 a = *(const float4*)(rowp + lh + q * 4);
            Xs[(lh + q * 4 + 0) * PITCH + le] = a.x;
            Xs[(lh + q * 4 + 1) * PITCH + le] = a.y;
            Xs[(lh + q * 4 + 2) * PITCH + le] = a.z;
            Xs[(lh + q * 4 + 3) * PITCH + le] = a.w;
        }
        const float* wrow = Wp + (size_t)(k0 + wkk) * 64 + woc;
        *(float4*)&Ws[wkk * 64 + woc]     = *(const float4*)(wrow);
        *(float4*)&Ws[wkk * 64 + woc + 4] = *(const float4*)(wrow + 4);
        __syncthreads();
#pragma unroll 16
        for (int kk = 0; kk < 32; kk++) {
            float4 w = *(const float4*)&Ws[kk * 64 + tx * 4];
            ull w0 = pack2(w.x, w.x), w1 = pack2(w.y, w.y);
            ull w2 = pack2(w.z, w.z), w3 = pack2(w.w, w.w);
            const ull* xp = (const ull*)&Xs[kk * PITCH + te * 8];
#pragma unroll
            for (int i = 0; i < 4; i++) {
                ull x = xp[i];
                acc[i][0] = fma2(x, w0, acc[i][0]);
                acc[i][1] = fma2(x, w1, acc[i][1]);
                acc[i][2] = fma2(x, w2, acc[i][2]);
                acc[i][3] = fma2(x, w3, acc[i][3]);
            }
        }
        __syncthreads();
    }
    {
        float4 bias = *(const float4*)&bp[tx * 4];
#pragma unroll
        for (int i = 0; i < 4; i++) {
            float2 c0 = unpack2(acc[i][0]), c1 = unpack2(acc[i][1]);
            float2 c2 = unpack2(acc[i][2]), c3 = unpack2(acc[i][3]);
            int pos = base + te * 8 + 2 * i;
            *(float4*)&g_msgp[(size_t)pos * 64 + tx * 4] =
                make_float4(c0.x + bias.x, c1.x + bias.y, c2.x + bias.z, c3.x + bias.w);
            *(float4*)&g_msgp[(size_t)(pos + 1) * 64 + tx * 4] =
                make_float4(c0.y + bias.x, c1.y + bias.y, c2.y + bias.z, c3.y + bias.w);
        }
    }
}

// ---------------- per-node PNA aggregation (warp per node, CSR segments) -------------
__global__ void k_agg() {
    int warp = (blockIdx.x * blockDim.x + threadIdx.x) >> 5;
    int l = threadIdx.x & 31;
    if (warp >= N) return;
    int n = warp;
    int s0 = g_offs[n];
    int s1 = g_offs[n + 1];
    int d = s1 - s0;

    float sm[4] = {0.f, 0.f, 0.f, 0.f};
    float sq[4] = {0.f, 0.f, 0.f, 0.f};
    float mx[4] = {-FLT_BIG, -FLT_BIG, -FLT_BIG, -FLT_BIG};
    float mn[4] = {FLT_BIG, FLT_BIG, FLT_BIG, FLT_BIG};

    for (int i = s0; i < s1; i++) {
        const float* rh = g_msgh + (size_t)i * 64;
        const float* rp = g_msgp + (size_t)i * 64;
        float v0 = rh[l];
        float v1 = rh[l + 32];
        float v2 = rp[l];
        float v3 = rp[l + 32];
        sm[0] += v0; sq[0] += v0 * v0; mx[0] = fmaxf(mx[0], v0); mn[0] = fminf(mn[0], v0);
        sm[1] += v1; sq[1] += v1 * v1; mx[1] = fmaxf(mx[1], v1); mn[1] = fminf(mn[1], v1);
        sm[2] += v2; sq[2] += v2 * v2; mx[2] = fmaxf(mx[2], v2); mn[2] = fminf(mn[2], v2);
        sm[3] += v3; sq[3] += v3 * v3; mx[3] = fmaxf(mx[3], v3); mn[3] = fminf(mn[3], v3);
    }

    float degc = fmaxf((float)d, 1.f);
    float inv = 1.f / degc;
    bool has = d > 0;
    float logd = has ? logf((float)d + 1.f) : 1.f;
    float amp = logd / AVG_D_LOG;
    float att = AVG_D_LOG / logd;

    float* outh = g_aggh + (size_t)n * 768;
    float* outp = g_aggp + (size_t)n * 768;

#pragma unroll
    for (int c = 0; c < 4; c++) {
        float mean = sm[c] * inv;
        float var = fmaxf(sq[c] * inv - mean * mean, 0.f);
        float sd = sqrtf(var + EPS_STD);
        float MX = has ? mx[c] : 0.f;
        float MN = has ? mn[c] : 0.f;
        float* o = (c < 2) ? outh : outp;
        int f = l + ((c & 1) ? 32 : 0);
        o[f] = mean;            o[64 + f] = MX;        o[128 + f] = MN;        o[192 + f] = sd;
        o[256 + f] = mean * amp; o[320 + f] = MX * amp; o[384 + f] = MN * amp; o[448 + f] = sd * amp;
        o[512 + f] = mean * att; o[576 + f] = MX * att; o[640 + f] = MN * att; o[704 + f] = sd * att;
    }
}

// ---------------- node GEMMs (f32x2 packed) ----------
__global__ void __launch_bounds__(256) k_nodegemm(
    const float* __restrict__ h, const float* __restrict__ p,
    const float* __restrict__ snorm,
    const float* __restrict__ Woh, const float* __restrict__ boh,
    const float* __restrict__ Wop, const float* __restrict__ bop,
    float* __restrict__ out)
{
    __shared__ __align__(16) float Xs[32 * PITCH];
    __shared__ __align__(16) float Ws[32 * 64];

    int tid = threadIdx.x;
    int base = blockIdx.x * 128;

    int tx = tid & 15;
    int te = tid >> 4;
    int le = tid & 127;
    int lh = (tid >> 7) * 16;
    int wkk = tid >> 3;
    int woc = (tid & 7) * 8;

    int nl = base + le;
    bool okl = nl < N;

    ull acc[4][4];

    // ============ phase H (K=896, 28 tiles) ============
#pragma unroll
    for (int i = 0; i < 4; i++)
#pragma unroll
        for (int j = 0; j < 4; j++) acc[i][j] = 0ull;

    for (int t = 0; t < 28; t++) {
        int k0 = t * 32;
        const float* rowp = (t < 4) ? (h + (size_t)nl * 128 + k0)
                                    : (g_aggh + (size_t)nl * 768 + (k0 - 128));
#pragma unroll
        for (int q = 0; q < 4; q++) {
            float4 a = okl ? *(const float4*)(rowp + lh + q * 4)
                           : make_float4(0.f, 0.f, 0.f, 0.f);
            Xs[(lh + q * 4 + 0) * PITCH + le] = a.x;
            Xs[(lh + q * 4 + 1) * PITCH + le] = a.y;
            Xs[(lh + q * 4 + 2) * PITCH + le] = a.z;
            Xs[(lh + q * 4 + 3) * PITCH + le] = a.w;
        }
        const float* wrow = Woh + (size_t)(k0 + wkk) * 64 + woc;
        *(float4*)&Ws[wkk * 64 + woc]     = *(const float4*)(wrow);
        *(float4*)&Ws[wkk * 64 + woc + 4] = *(const float4*)(wrow + 4);
        __syncthreads();
#pragma unroll 16
        for (int kk = 0; kk < 32; kk++) {
            float4 w = *(const float4*)&Ws[kk * 64 + tx * 4];
            ull w0 = pack2(w.x, w.x), w1 = pack2(w.y, w.y);
            ull w2 = pack2(w.z, w.z), w3 = pack2(w.w, w.w);
            const ull* xp = (const ull*)&Xs[kk * PITCH + te * 8];
#pragma unroll
            for (int i = 0; i < 4; i++) {
                ull x = xp[i];
                acc[i][0] = fma2(x, w0, acc[i][0]);
                acc[i][1] = fma2(x, w1, acc[i][1]);
                acc[i][2] = fma2(x, w2, acc[i][2]);
                acc[i][3] = fma2(x, w3, acc[i][3]);
            }
        }
        __syncthreads();
    }
    {
        float4 bias = *(const float4*)&boh[tx * 4];
#pragma unroll
        for (int i = 0; i < 4; i++) {
            float2 c0 = unpack2(acc[i][0]), c1 = unpack2(acc[i][1]);
            float2 c2 = unpack2(acc[i][2]), c3 = unpack2(acc[i][3]);
            int n0 = base + te * 8 + 2 * i;
            if (n0 < N) {
                float sn = snorm[n0];
                *(float4*)&out[(size_t)n0 * 64 + tx * 4] =
                    make_float4((c0.x + bias.x) * sn, (c1.x + bias.y) * sn,
                                (c2.x + bias.z) * sn, (c3.x + bias.w) * sn);
            }
            if (n0 + 1 < N) {
                float sn = snorm[n0 + 1];
                *(float4*)&out[(size_t)(n0 + 1) * 64 + tx * 4] =
                    make_float4((c0.y + bias.x) * sn, (c1.y + bias.y) * sn,
                                (c2.y + bias.z) * sn, (c3.y + bias.w) * sn);
            }
        }
    }

    // ============ phase P (K=832, 26 tiles) ============
#pragma unroll
    for (int i = 0; i < 4; i++)
#pragma unroll
        for (int j = 0; j < 4; j++) acc[i][j] = 0ull;

    for (int t = 0; t < 26; t++) {
        int k0 = t * 32;
        const float* rowp = (t < 2) ? (p + (size_t)nl * 64 + k0)
                                    : (g_aggp + (size_t)nl * 768 + (k0 - 64));
#pragma unroll
        for (int q = 0; q < 4; q++) {
            float4 a = okl ? *(const float4*)(rowp + lh + q * 4)
                           : make_float4(0.f, 0.f, 0.f, 0.f);
            Xs[(lh + q * 4 + 0) * PITCH + le] = a.x;
            Xs[(lh + q * 4 + 1) * PITCH + le] = a.y;
            Xs[(lh + q * 4 + 2) * PITCH + le] = a.z;
            Xs[(lh + q * 4 + 3) * PITCH + le] = a.w;
        }
        const float* wrow = Wop + (size_t)(k0 + wkk) * 64 + woc;
        *(float4*)&Ws[wkk * 64 + woc]     = *(const float4*)(wrow);
        *(float4*)&Ws[wkk * 64 + woc + 4] = *(const float4*)(wrow + 4);
        __syncthreads();
#pragma unroll 16
        for (int kk = 0; kk < 32; kk++) {
            float4 w = *(const float4*)&Ws[kk * 64 + tx * 4];
            ull w0 = pack2(w.x, w.x), w1 = pack2(w.y, w.y);
            ull w2 = pack2(w.z, w.z), w3 = pack2(w.w, w.w);
            const ull* xp = (const ull*)&Xs[kk * PITCH + te * 8];
#pragma unroll
            for (int i = 0; i < 4; i++) {
                ull x = xp[i];
                acc[i][0] = fma2(x, w0, acc[i][0]);
                acc[i][1] = fma2(x, w1, acc[i][1]);
                acc[i][2] = fma2(x, w2, acc[i][2]);
                acc[i][3] = fma2(x, w3, acc[i][3]);
            }
        }
        __syncthreads();
    }
    {
        float4 bias = *(const float4*)&bop[tx * 4];
        float* outp = out + (size_t)N * 64;
#pragma unroll
        for (int i = 0; i < 4; i++) {
            float2 c0 = unpack2(acc[i][0]), c1 = unpack2(acc[i][1]);
            float2 c2 = unpack2(acc[i][2]), c3 = unpack2(acc[i][3]);
            int n0 = base + te * 8 + 2 * i;
            if (n0 < N)
                *(float4*)&outp[(size_t)n0 * 64 + tx * 4] =
                    make_float4(c0.x + bias.x, c1.x + bias.y, c2.x + bias.z, c3.x + bias.w);
            if (n0 + 1 < N)
                *(float4*)&outp[(size_t)(n0 + 1) * 64 + tx * 4] =
                    make_float4(c0.y + bias.x, c1.y + bias.y, c2.y + bias.z, c3.y + bias.w);
        }
    }
}

// ---------------- batchnorm stats ----------------
__global__ void k_bnstats(const float* __restrict__ out) {
    __shared__ float ss[4][64];
    __shared__ float sqv[4][64];
    int f = threadIdx.x & 63;
    int rg = threadIdx.x >> 6;
    int r0 = blockIdx.x * 128;
    int rend = r0 + 128;
    if (rend > N) rend = N;
    float s = 0.f, q = 0.f;
    for (int r = r0 + rg; r < rend; r += 4) {
        float x = out[(size_t)r * 64 + f];
        s += x; q += x * x;
    }
    ss[rg][f] = s; sqv[rg][f] = q;
    __syncthreads();
    if (threadIdx.x < 64) {
        float S = ss[0][f] + ss[1][f] + ss[2][f] + ss[3][f];
        float Q = sqv[0][f] + sqv[1][f] + sqv[2][f] + sqv[3][f];
        atomicAdd(&g_bnsum[f], S);
        atomicAdd(&g_bnsq[f], Q);
    }
}

// ---------------- batchnorm apply ----------------
__global__ void k_bnapply(float* __restrict__ out,
                          const float* __restrict__ gamma,
                          const float* __restrict__ beta) {
    int i = blockIdx.x * blockDim.x + threadIdx.x;
    if (i >= N * 64) return;
    int f = i & 63;
    const float invN = 1.f / (float)N;
    float mu = g_bnsum[f] * invN;
    float var = g_bnsq[f] * invN - mu * mu;
    float x = out[i];
    out[i] = (x - mu) * rsqrtf(var + EPS_BN) * gamma[f] + beta[f];
}

} // namespace

extern "C" void kernel_launch(void* const* d_in, const int* in_sizes, int n_in,
                              void* d_out, int out_size) {
    const float* h     = (const float*)d_in[0];
    const float* p     = (const float*)d_in[1];
    const float* e     = (const float*)d_in[2];
    const int*   src   = (const int*)d_in[3];
    const int*   dst   = (const int*)d_in[4];
    const float* snorm = (const float*)d_in[5];
    const float* Wph   = (const float*)d_in[6];
    const float* bph   = (const float*)d_in[7];
    const float* Wpp   = (const float*)d_in[8];
    const float* bpp   = (const float*)d_in[9];
    const float* Woh   = (const float*)d_in[10];
    const float* boh   = (const float*)d_in[11];
    const float* Wop   = (const float*)d_in[12];
    const float* bop   = (const float*)d_in[13];
    const float* gamma = (const float*)d_in[14];
    const float* beta  = (const float*)d_in[15];
    float* out = (float*)d_out;

    k_init<<<(N + 255) / 256, 256>>>();
    k_hist<<<(E + 255) / 256, 256>>>(dst);
    k_scan<<<1, 1024>>>();
    k_scatter<<<(E + 255) / 256, 256>>>(dst);
    k_edgegemm<<<E / 128, 256>>>(h, p, e, src, dst, Wph, bph, Wpp, bpp);
    k_agg<<<(N * 32 + 255) / 256, 256>>>();
    k_nodegemm<<<(N + 127) / 128, 256>>>(h, p, snorm, Woh, boh, Wop, bop, out);
    k_bnstats<<<(N + 127) / 128, 256>>>(out);
    k_bnapply<<<(N * 64 + 255) / 256, 256>>>(out, gamma, beta);
}

// round 3
// speedup vs baseline: 2.4504x; 1.9140x over previous
#include <cuda_runtime.h>
#include <math.h>

namespace {

constexpr int N = 50000;
constexpr int E = 800000;
constexpr float AVG_D_LOG = 2.8332f;
constexpr float EPS_STD = 1e-5f;
constexpr float EPS_BN = 1e-5f;
constexpr float FLT_BIG = 3.402823466e+38f;
constexpr int PITCH = 130;     // k-major Xs pitch (floats)

typedef unsigned long long ull;

__device__ __forceinline__ ull fma2(ull a, ull b, ull c) {
    ull d;
    asm("fma.rn.f32x2 %0,%1,%2,%3;" : "=l"(d) : "l"(a), "l"(b), "l"(c));
    return d;
}
__device__ __forceinline__ ull pack2(float x, float y) {
    ull d;
    asm("mov.b64 %0,{%1,%2};" : "=l"(d) : "f"(x), "f"(y));
    return d;
}
__device__ __forceinline__ float2 unpack2(ull v) {
    float2 r;
    asm("mov.b64 {%0,%1},%2;" : "=f"(r.x), "=f"(r.y) : "l"(v));
    return r;
}

// ---- scratch (device globals: allocation-free contract) ----
__device__ int g_deg[N];
__device__ int g_offs[N + 1];
__device__ int g_cursor[N];
__device__ int g_perm[E];
__device__ int g_srcs[E];                                // src id at sorted position
__device__ __align__(16) float g_Ah[(size_t)N * 64];     // h @ W1
__device__ __align__(16) float g_Bh[(size_t)N * 64];     // h @ W2
__device__ __align__(16) float g_Ap[(size_t)N * 64];     // p @ P1
__device__ __align__(16) float g_Bp[(size_t)N * 64];     // p @ P2
__device__ __align__(16) float g_ceh[(size_t)E * 64];    // e @ W3 + b  (sorted order)
__device__ __align__(16) float g_cep[(size_t)E * 64];
__device__ __align__(16) float g_aggh[(size_t)N * 768];
__device__ __align__(16) float g_aggp[(size_t)N * 768];
__device__ float g_bnsum[64];
__device__ float g_bnsq[64];

// ---------------- init ----------------
__global__ void k_init() {
    int i = blockIdx.x * blockDim.x + threadIdx.x;
    if (i < N) g_deg[i] = 0;
    if (i < 64) { g_bnsum[i] = 0.f; g_bnsq[i] = 0.f; }
}

// ---------------- degree histogram ----------------
__global__ void k_hist(const int* __restrict__ dst) {
    int e = blockIdx.x * blockDim.x + threadIdx.x;
    if (e < E) atomicAdd(&g_deg[dst[e]], 1);
}

// ---------------- exclusive scan (single block) ----------------
__global__ void k_scan() {
    __shared__ int s[1024];
    int t = threadIdx.x;
    int carry = 0;
    for (int base = 0; base < N; base += 1024) {
        int v = (base + t < N) ? g_deg[base + t] : 0;
        s[t] = v;
        __syncthreads();
        for (int off = 1; off < 1024; off <<= 1) {
            int add = (t >= off) ? s[t - off] : 0;
            __syncthreads();
            s[t] += add;
            __syncthreads();
        }
        int incl = s[t];
        if (base + t < N) {
            int ex = carry + incl - v;
            g_offs[base + t] = ex;
            g_cursor[base + t] = ex;
        }
        carry += s[1023];
        __syncthreads();
    }
    if (t == 0) g_offs[N] = carry;
}

// ---------------- scatter: counting sort by dst ----------------
__global__ void k_scatter(const int* __restrict__ dst, const int* __restrict__ src) {
    int e = blockIdx.x * blockDim.x + threadIdx.x;
    if (e < E) {
        int pos = atomicAdd(&g_cursor[dst[e]], 1);
        g_perm[pos] = e;
        g_srcs[pos] = src[e];
    }
}

// ---------------- node pre-GEMMs: Ah=h@W1, Bh=h@W2, Ap=p@P1, Bp=p@P2 --------------
// 128 nodes x (64+64) outs per block. Dual accumulators share the X tile.
__global__ void __launch_bounds__(256) k_nodepre(
    const float* __restrict__ h, const float* __restrict__ p,
    const float* __restrict__ Wh, const float* __restrict__ Wp)
{
    __shared__ __align__(16) float Xs[32 * PITCH];
    __shared__ __align__(16) float Ws[32 * 128];

    int tid = threadIdx.x;
    int base = blockIdx.x * 128;

    int tx = tid & 15;
    int te = tid >> 4;
    int le = tid & 127;
    int lh = (tid >> 7) * 16;
    int wkk = tid >> 3;          // 0..31
    int woc = (tid & 7) * 16;    // 0,16,...,112

    int nl = base + le;
    bool okl = nl < N;

    ull acca[4][4], accb[4][4];

    // ===== h phase: Ah (W rows 0..127), Bh (W rows 128..255), K=128 =====
#pragma unroll
    for (int i = 0; i < 4; i++)
#pragma unroll
        for (int j = 0; j < 4; j++) { acca[i][j] = 0ull; accb[i][j] = 0ull; }

    for (int t = 0; t < 4; t++) {
        int k0 = t * 32;
        const float* rowp = h + (size_t)nl * 128 + k0;
#pragma unroll
        for (int q = 0; q < 4; q++) {
            float4 a = okl ? *(const float4*)(rowp + lh + q * 4)
                           : make_float4(0.f, 0.f, 0.f, 0.f);
            Xs[(lh + q * 4 + 0) * PITCH + le] = a.x;
            Xs[(lh + q * 4 + 1) * PITCH + le] = a.y;
            Xs[(lh + q * 4 + 2) * PITCH + le] = a.z;
            Xs[(lh + q * 4 + 3) * PITCH + le] = a.w;
        }
        {
            const float* wr = (woc < 64) ? (Wh + (size_t)(k0 + wkk) * 64 + woc)
                                         : (Wh + (size_t)(128 + k0 + wkk) * 64 + (woc - 64));
#pragma unroll
            for (int q = 0; q < 4; q++)
                *(float4*)&Ws[wkk * 128 + woc + q * 4] = *(const float4*)(wr + q * 4);
        }
        __syncthreads();
#pragma unroll 16
        for (int kk = 0; kk < 32; kk++) {
            float4 wa = *(const float4*)&Ws[kk * 128 + tx * 4];
            float4 wb = *(const float4*)&Ws[kk * 128 + 64 + tx * 4];
            ull a0 = pack2(wa.x, wa.x), a1 = pack2(wa.y, wa.y);
            ull a2 = pack2(wa.z, wa.z), a3 = pack2(wa.w, wa.w);
            ull b0 = pack2(wb.x, wb.x), b1 = pack2(wb.y, wb.y);
            ull b2 = pack2(wb.z, wb.z), b3 = pack2(wb.w, wb.w);
            const ull* xp = (const ull*)&Xs[kk * PITCH + te * 8];
#pragma unroll
            for (int i = 0; i < 4; i++) {
                ull x = xp[i];
                acca[i][0] = fma2(x, a0, acca[i][0]);
                acca[i][1] = fma2(x, a1, acca[i][1]);
                acca[i][2] = fma2(x, a2, acca[i][2]);
                acca[i][3] = fma2(x, a3, acca[i][3]);
                accb[i][0] = fma2(x, b0, accb[i][0]);
                accb[i][1] = fma2(x, b1, accb[i][1]);
                accb[i][2] = fma2(x, b2, accb[i][2]);
                accb[i][3] = fma2(x, b3, accb[i][3]);
            }
        }
        __syncthreads();
    }
#pragma unroll
    for (int i = 0; i < 4; i++) {
        float2 a0 = unpack2(acca[i][0]), a1 = unpack2(acca[i][1]);
        float2 a2 = unpack2(acca[i][2]), a3 = unpack2(acca[i][3]);
        float2 b0 = unpack2(accb[i][0]), b1 = unpack2(accb[i][1]);
        float2 b2 = unpack2(accb[i][2]), b3 = unpack2(accb[i][3]);
        int n0 = base + te * 8 + 2 * i;
        if (n0 < N) {
            *(float4*)&g_Ah[(size_t)n0 * 64 + tx * 4] = make_float4(a0.x, a1.x, a2.x, a3.x);
            *(float4*)&g_Bh[(size_t)n0 * 64 + tx * 4] = make_float4(b0.x, b1.x, b2.x, b3.x);
        }
        if (n0 + 1 < N) {
            *(float4*)&g_Ah[(size_t)(n0 + 1) * 64 + tx * 4] = make_float4(a0.y, a1.y, a2.y, a3.y);
            *(float4*)&g_Bh[(size_t)(n0 + 1) * 64 + tx * 4] = make_float4(b0.y, b1.y, b2.y, b3.y);
        }
    }

    // ===== p phase: Ap (P rows 0..63), Bp (P rows 64..127), K=64 =====
#pragma unroll
    for (int i = 0; i < 4; i++)
#pragma unroll
        for (int j = 0; j < 4; j++) { acca[i][j] = 0ull; accb[i][j] = 0ull; }

    for (int t = 0; t < 2; t++) {
        int k0 = t * 32;
        const float* rowp = p + (size_t)nl * 64 + k0;
#pragma unroll
        for (int q = 0; q < 4; q++) {
            float4 a = okl ? *(const float4*)(rowp + lh + q * 4)
                           : make_float4(0.f, 0.f, 0.f, 0.f);
            Xs[(lh + q * 4 + 0) * PITCH + le] = a.x;
            Xs[(lh + q * 4 + 1) * PITCH + le] = a.y;
            Xs[(lh + q * 4 + 2) * PITCH + le] = a.z;
            Xs[(lh + q * 4 + 3) * PITCH + le] = a.w;
        }
        {
            const float* wr = (woc < 64) ? (Wp + (size_t)(k0 + wkk) * 64 + woc)
                                         : (Wp + (size_t)(64 + k0 + wkk) * 64 + (woc - 64));
#pragma unroll
            for (int q = 0; q < 4; q++)
                *(float4*)&Ws[wkk * 128 + woc + q * 4] = *(const float4*)(wr + q * 4);
        }
        __syncthreads();
#pragma unroll 16
        for (int kk = 0; kk < 32; kk++) {
            float4 wa = *(const float4*)&Ws[kk * 128 + tx * 4];
            float4 wb = *(const float4*)&Ws[kk * 128 + 64 + tx * 4];
            ull a0 = pack2(wa.x, wa.x), a1 = pack2(wa.y, wa.y);
            ull a2 = pack2(wa.z, wa.z), a3 = pack2(wa.w, wa.w);
            ull b0 = pack2(wb.x, wb.x), b1 = pack2(wb.y, wb.y);
            ull b2 = pack2(wb.z, wb.z), b3 = pack2(wb.w, wb.w);
            const ull* xp = (const ull*)&Xs[kk * PITCH + te * 8];
#pragma unroll
            for (int i = 0; i < 4; i++) {
                ull x = xp[i];
                acca[i][0] = fma2(x, a0, acca[i][0]);
                acca[i][1] = fma2(x, a1, acca[i][1]);
                acca[i][2] = fma2(x, a2, acca[i][2]);
                acca[i][3] = fma2(x, a3, acca[i][3]);
                accb[i][0] = fma2(x, b0, accb[i][0]);
                accb[i][1] = fma2(x, b1, accb[i][1]);
                accb[i][2] = fma2(x, b2, accb[i][2]);
                accb[i][3] = fma2(x, b3, accb[i][3]);
            }
        }
        __syncthreads();
    }
#pragma unroll
    for (int i = 0; i < 4; i++) {
        float2 a0 = unpack2(acca[i][0]), a1 = unpack2(acca[i][1]);
        float2 a2 = unpack2(acca[i][2]), a3 = unpack2(acca[i][3]);
        float2 b0 = unpack2(accb[i][0]), b1 = unpack2(accb[i][1]);
        float2 b2 = unpack2(accb[i][2]), b3 = unpack2(accb[i][3]);
        int n0 = base + te * 8 + 2 * i;
        if (n0 < N) {
            *(float4*)&g_Ap[(size_t)n0 * 64 + tx * 4] = make_float4(a0.x, a1.x, a2.x, a3.x);
            *(float4*)&g_Bp[(size_t)n0 * 64 + tx * 4] = make_float4(b0.x, b1.x, b2.x, b3.x);
        }
        if (n0 + 1 < N) {
            *(float4*)&g_Ap[(size_t)(n0 + 1) * 64 + tx * 4] = make_float4(a0.y, a1.y, a2.y, a3.y);
            *(float4*)&g_Bp[(size_t)(n0 + 1) * 64 + tx * 4] = make_float4(b0.y, b1.y, b2.y, b3.y);
        }
    }
}

// ---------------- edge-feature GEMM: Ceh = e@W3 + bh, Cep = e@P3 + bp (sorted) -------
__global__ void __launch_bounds__(256) k_edgeE(
    const float* __restrict__ ef,
    const float* __restrict__ Wh, const float* __restrict__ bh,
    const float* __restrict__ Wp, const float* __restrict__ bp)
{
    __shared__ __align__(16) float Xs[32 * PITCH];
    __shared__ __align__(16) float Ws[32 * 128];
    __shared__ int s_eid[128];

    int tid = threadIdx.x;
    int base = blockIdx.x * 128;

    for (int j = tid; j < 128; j += 256) s_eid[j] = g_perm[base + j];

    int tx = tid & 15;
    int te = tid >> 4;
    int le = tid & 127;
    int lh = (tid >> 7) * 16;
    int wkk = tid >> 3;
    int woc = (tid & 7) * 16;

    {
        const float* wr = (woc < 64) ? (Wh + (size_t)(256 + wkk) * 64 + woc)
                                     : (Wp + (size_t)(128 + wkk) * 64 + (woc - 64));
#pragma unroll
        for (int q = 0; q < 4; q++)
            *(float4*)&Ws[wkk * 128 + woc + q * 4] = *(const float4*)(wr + q * 4);
    }
    __syncthreads();
    {
        const float* rowp = ef + (size_t)s_eid[le] * 32;
#pragma unroll
        for (int q = 0; q < 4; q++) {
            float4 a = *(const float4*)(rowp + lh + q * 4);
            Xs[(lh + q * 4 + 0) * PITCH + le] = a.x;
            Xs[(lh + q * 4 + 1) * PITCH + le] = a.y;
            Xs[(lh + q * 4 + 2) * PITCH + le] = a.z;
            Xs[(lh + q * 4 + 3) * PITCH + le] = a.w;
        }
    }
    __syncthreads();

    ull acca[4][4], accb[4][4];
#pragma unroll
    for (int i = 0; i < 4; i++)
#pragma unroll
        for (int j = 0; j < 4; j++) { acca[i][j] = 0ull; accb[i][j] = 0ull; }

#pragma unroll 16
    for (int kk = 0; kk < 32; kk++) {
        float4 wa = *(const float4*)&Ws[kk * 128 + tx * 4];
        float4 wb = *(const float4*)&Ws[kk * 128 + 64 + tx * 4];
        ull a0 = pack2(wa.x, wa.x), a1 = pack2(wa.y, wa.y);
        ull a2 = pack2(wa.z, wa.z), a3 = pack2(wa.w, wa.w);
        ull b0 = pack2(wb.x, wb.x), b1 = pack2(wb.y, wb.y);
        ull b2 = pack2(wb.z, wb.z), b3 = pack2(wb.w, wb.w);
        const ull* xp = (const ull*)&Xs[kk * PITCH + te * 8];
#pragma unroll
        for (int i = 0; i < 4; i++) {
            ull x = xp[i];
            acca[i][0] = fma2(x, a0, acca[i][0]);
            acca[i][1] = fma2(x, a1, acca[i][1]);
            acca[i][2] = fma2(x, a2, acca[i][2]);
            acca[i][3] = fma2(x, a3, acca[i][3]);
            accb[i][0] = fma2(x, b0, accb[i][0]);
            accb[i][1] = fma2(x, b1, accb[i][1]);
            accb[i][2] = fma2(x, b2, accb[i][2]);
            accb[i][3] = fma2(x, b3, accb[i][3]);
        }
    }

    float4 biash = *(const float4*)&bh[tx * 4];
    float4 biasp = *(const float4*)&bp[tx * 4];
#pragma unroll
    for (int i = 0; i < 4; i++) {
        float2 a0 = unpack2(acca[i][0]), a1 = unpack2(acca[i][1]);
        float2 a2 = unpack2(acca[i][2]), a3 = unpack2(acca[i][3]);
        float2 b0 = unpack2(accb[i][0]), b1 = unpack2(accb[i][1]);
        float2 b2 = unpack2(accb[i][2]), b3 = unpack2(accb[i][3]);
        int pos = base + te * 8 + 2 * i;
        *(float4*)&g_ceh[(size_t)pos * 64 + tx * 4] =
            make_float4(a0.x + biash.x, a1.x + biash.y, a2.x + biash.z, a3.x + biash.w);
        *(float4*)&g_ceh[(size_t)(pos + 1) * 64 + tx * 4] =
            make_float4(a0.y + biash.x, a1.y + biash.y, a2.y + biash.z, a3.y + biash.w);
        *(float4*)&g_cep[(size_t)pos * 64 + tx * 4] =
            make_float4(b0.x + biasp.x, b1.x + biasp.y, b2.x + biasp.z, b3.x + biasp.w);
        *(float4*)&g_cep[(size_t)(pos + 1) * 64 + tx * 4] =
            make_float4(b0.y + biasp.x, b1.y + biasp.y, b2.y + biasp.z, b3.y + biasp.w);
    }
}

// ---------------- fused message + PNA aggregation (warp per node) -------------
__global__ void k_agg() {
    int warp = (blockIdx.x * blockDim.x + threadIdx.x) >> 5;
    int l = threadIdx.x & 31;
    if (warp >= N) return;
    int n = warp;
    int s0 = g_offs[n];
    int s1 = g_offs[n + 1];
    int d = s1 - s0;

    float bh0 = g_Bh[(size_t)n * 64 + l];
    float bh1 = g_Bh[(size_t)n * 64 + l + 32];
    float bp0 = g_Bp[(size_t)n * 64 + l];
    float bp1 = g_Bp[(size_t)n * 64 + l + 32];

    float sm[4] = {0.f, 0.f, 0.f, 0.f};
    float sq[4] = {0.f, 0.f, 0.f, 0.f};
    float mx[4] = {-FLT_BIG, -FLT_BIG, -FLT_BIG, -FLT_BIG};
    float mn[4] = {FLT_BIG, FLT_BIG, FLT_BIG, FLT_BIG};

    for (int i = s0; i < s1; i++) {
        int s = g_srcs[i];
        const float* ah = g_Ah + (size_t)s * 64;
        const float* ap = g_Ap + (size_t)s * 64;
        const float* ch = g_ceh + (size_t)i * 64;
        const float* cp = g_cep + (size_t)i * 64;
        float v0 = ch[l]      + ah[l]      + bh0;
        float v1 = ch[l + 32] + ah[l + 32] + bh1;
        float v2 = cp[l]      + ap[l]      + bp0;
        float v3 = cp[l + 32] + ap[l + 32] + bp1;
        sm[0] += v0; sq[0] += v0 * v0; mx[0] = fmaxf(mx[0], v0); mn[0] = fminf(mn[0], v0);
        sm[1] += v1; sq[1] += v1 * v1; mx[1] = fmaxf(mx[1], v1); mn[1] = fminf(mn[1], v1);
        sm[2] += v2; sq[2] += v2 * v2; mx[2] = fmaxf(mx[2], v2); mn[2] = fminf(mn[2], v2);
        sm[3] += v3; sq[3] += v3 * v3; mx[3] = fmaxf(mx[3], v3); mn[3] = fminf(mn[3], v3);
    }

    float degc = fmaxf((float)d, 1.f);
    float inv = 1.f / degc;
    bool has = d > 0;
    float logd = has ? logf((float)d + 1.f) : 1.f;
    float amp = logd / AVG_D_LOG;
    float att = AVG_D_LOG / logd;

    float* outh = g_aggh + (size_t)n * 768;
    float* outp = g_aggp + (size_t)n * 768;

#pragma unroll
    for (int c = 0; c < 4; c++) {
        float mean = sm[c] * inv;
        float var = fmaxf(sq[c] * inv - mean * mean, 0.f);
        float sd = sqrtf(var + EPS_STD);
        float MX = has ? mx[c] : 0.f;
        float MN = has ? mn[c] : 0.f;
        float* o = (c < 2) ? outh : outp;
        int f = l + ((c & 1) ? 32 : 0);
        o[f] = mean;            o[64 + f] = MX;        o[128 + f] = MN;        o[192 + f] = sd;
        o[256 + f] = mean * amp; o[320 + f] = MX * amp; o[384 + f] = MN * amp; o[448 + f] = sd * amp;
        o[512 + f] = mean * att; o[576 + f] = MX * att; o[640 + f] = MN * att; o[704 + f] = sd * att;
    }
}

// ---------------- node GEMMs (f32x2 packed) ----------
__global__ void __launch_bounds__(256) k_nodegemm(
    const float* __restrict__ h, const float* __restrict__ p,
    const float* __restrict__ snorm,
    const float* __restrict__ Woh, const float* __restrict__ boh,
    const float* __restrict__ Wop, const float* __restrict__ bop,
    float* __restrict__ out)
{
    __shared__ __align__(16) float Xs[32 * PITCH];
    __shared__ __align__(16) float Ws[32 * 64];

    int tid = threadIdx.x;
    int base = blockIdx.x * 128;

    int tx = tid & 15;
    int te = tid >> 4;
    int le = tid & 127;
    int lh = (tid >> 7) * 16;
    int wkk = tid >> 3;
    int woc = (tid & 7) * 8;

    int nl = base + le;
    bool okl = nl < N;

    ull acc[4][4];

    // ============ phase H (K=896, 28 tiles) ============
#pragma unroll
    for (int i = 0; i < 4; i++)
#pragma unroll
        for (int j = 0; j < 4; j++) acc[i][j] = 0ull;

    for (int t = 0; t < 28; t++) {
        int k0 = t * 32;
        const float* rowp = (t < 4) ? (h + (size_t)nl * 128 + k0)
                                    : (g_aggh + (size_t)nl * 768 + (k0 - 128));
#pragma unroll
        for (int q = 0; q < 4; q++) {
            float4 a = okl ? *(const float4*)(rowp + lh + q * 4)
                           : make_float4(0.f, 0.f, 0.f, 0.f);
            Xs[(lh + q * 4 + 0) * PITCH + le] = a.x;
            Xs[(lh + q * 4 + 1) * PITCH + le] = a.y;
            Xs[(lh + q * 4 + 2) * PITCH + le] = a.z;
            Xs[(lh + q * 4 + 3) * PITCH + le] = a.w;
        }
        const float* wrow = Woh + (size_t)(k0 + wkk) * 64 + woc;
        *(float4*)&Ws[wkk * 64 + woc]     = *(const float4*)(wrow);
        *(float4*)&Ws[wkk * 64 + woc + 4] = *(const float4*)(wrow + 4);
        __syncthreads();
#pragma unroll 16
        for (int kk = 0; kk < 32; kk++) {
            float4 w = *(const float4*)&Ws[kk * 64 + tx * 4];
            ull w0 = pack2(w.x, w.x), w1 = pack2(w.y, w.y);
            ull w2 = pack2(w.z, w.z), w3 = pack2(w.w, w.w);
            const ull* xp = (const ull*)&Xs[kk * PITCH + te * 8];
#pragma unroll
            for (int i = 0; i < 4; i++) {
                ull x = xp[i];
                acc[i][0] = fma2(x, w0, acc[i][0]);
                acc[i][1] = fma2(x, w1, acc[i][1]);
                acc[i][2] = fma2(x, w2, acc[i][2]);
                acc[i][3] = fma2(x, w3, acc[i][3]);
            }
        }
        __syncthreads();
    }
    {
        float4 bias = *(const float4*)&boh[tx * 4];
#pragma unroll
        for (int i = 0; i < 4; i++) {
            float2 c0 = unpack2(acc[i][0]), c1 = unpack2(acc[i][1]);
            float2 c2 = unpack2(acc[i][2]), c3 = unpack2(acc[i][3]);
            int n0 = base + te * 8 + 2 * i;
            if (n0 < N) {
                float sn = snorm[n0];
                *(float4*)&out[(size_t)n0 * 64 + tx * 4] =
                    make_float4((c0.x + bias.x) * sn, (c1.x + bias.y) * sn,
                                (c2.x + bias.z) * sn, (c3.x + bias.w) * sn);
            }
            if (n0 + 1 < N) {
                float sn = snorm[n0 + 1];
                *(float4*)&out[(size_t)(n0 + 1) * 64 + tx * 4] =
                    make_float4((c0.y + bias.x) * sn, (c1.y + bias.y) * sn,
                                (c2.y + bias.z) * sn, (c3.y + bias.w) * sn);
            }
        }
    }

    // ============ phase P (K=832, 26 tiles) ============
#pragma unroll
    for (int i = 0; i < 4; i++)
#pragma unroll
        for (int j = 0; j < 4; j++) acc[i][j] = 0ull;

    for (int t = 0; t < 26; t++) {
        int k0 = t * 32;
        const float* rowp = (t < 2) ? (p + (size_t)nl * 64 + k0)
                                    : (g_aggp + (size_t)nl * 768 + (k0 - 64));
#pragma unroll
        for (int q = 0; q < 4; q++) {
            float4 a = okl ? *(const float4*)(rowp + lh + q * 4)
                           : make_float4(0.f, 0.f, 0.f, 0.f);
            Xs[(lh + q * 4 + 0) * PITCH + le] = a.x;
            Xs[(lh + q * 4 + 1) * PITCH + le] = a.y;
            Xs[(lh + q * 4 + 2) * PITCH + le] = a.z;
            Xs[(lh + q * 4 + 3) * PITCH + le] = a.w;
        }
        const float* wrow = Wop + (size_t)(k0 + wkk) * 64 + woc;
        *(float4*)&Ws[wkk * 64 + woc]     = *(const float4*)(wrow);
        *(float4*)&Ws[wkk * 64 + woc + 4] = *(const float4*)(wrow + 4);
        __syncthreads();
#pragma unroll 16
        for (int kk = 0; kk < 32; kk++) {
            float4 w = *(const float4*)&Ws[kk * 64 + tx * 4];
            ull w0 = pack2(w.x, w.x), w1 = pack2(w.y, w.y);
            ull w2 = pack2(w.z, w.z), w3 = pack2(w.w, w.w);
            const ull* xp = (const ull*)&Xs[kk * PITCH + te * 8];
#pragma unroll
            for (int i = 0; i < 4; i++) {
                ull x = xp[i];
                acc[i][0] = fma2(x, w0, acc[i][0]);
                acc[i][1] = fma2(x, w1, acc[i][1]);
                acc[i][2] = fma2(x, w2, acc[i][2]);
                acc[i][3] = fma2(x, w3, acc[i][3]);
            }
        }
        __syncthreads();
    }
    {
        float4 bias = *(const float4*)&bop[tx * 4];
        float* outp = out + (size_t)N * 64;
#pragma unroll
        for (int i = 0; i < 4; i++) {
            float2 c0 = unpack2(acc[i][0]), c1 = unpack2(acc[i][1]);
            float2 c2 = unpack2(acc[i][2]), c3 = unpack2(acc[i][3]);
            int n0 = base + te * 8 + 2 * i;
            if (n0 < N)
                *(float4*)&outp[(size_t)n0 * 64 + tx * 4] =
                    make_float4(c0.x + bias.x, c1.x + bias.y, c2.x + bias.z, c3.x + bias.w);
            if (n0 + 1 < N)
                *(float4*)&outp[(size_t)(n0 + 1) * 64 + tx * 4] =
                    make_float4(c0.y + bias.x, c1.y + bias.y, c2.y + bias.z, c3.y + bias.w);
        }
    }
}

// ---------------- batchnorm stats ----------------
__global__ void k_bnstats(const float* __restrict__ out) {
    __shared__ float ss[4][64];
    __shared__ float sqv[4][64];
    int f = threadIdx.x & 63;
    int rg = threadIdx.x >> 6;
    int r0 = blockIdx.x * 128;
    int rend = r0 + 128;
    if (rend > N) rend = N;
    float s = 0.f, q = 0.f;
    for (int r = r0 + rg; r < rend; r += 4) {
        float x = out[(size_t)r * 64 + f];
        s += x; q += x * x;
    }
    ss[rg][f] = s; sqv[rg][f] = q;
    __syncthreads();
    if (threadIdx.x < 64) {
        float S = ss[0][f] + ss[1][f] + ss[2][f] + ss[3][f];
        float Q = sqv[0][f] + sqv[1][f] + sqv[2][f] + sqv[3][f];
        atomicAdd(&g_bnsum[f], S);
        atomicAdd(&g_bnsq[f], Q);
    }
}

// ---------------- batchnorm apply ----------------
__global__ void k_bnapply(float* __restrict__ out,
                          const float* __restrict__ gamma,
                          const float* __restrict__ beta) {
    int i = blockIdx.x * blockDim.x + threadIdx.x;
    if (i >= N * 64) return;
    int f = i & 63;
    const float invN = 1.f / (float)N;
    float mu = g_bnsum[f] * invN;
    float var = g_bnsq[f] * invN - mu * mu;
    float x = out[i];
    out[i] = (x - mu) * rsqrtf(var + EPS_BN) * gamma[f] + beta[f];
}

} // namespace

extern "C" void kernel_launch(void* const* d_in, const int* in_sizes, int n_in,
                              void* d_out, int out_size) {
    const float* h     = (const float*)d_in[0];
    const float* p     = (const float*)d_in[1];
    const float* e     = (const float*)d_in[2];
    const int*   src   = (const int*)d_in[3];
    const int*   dst   = (const int*)d_in[4];
    const float* snorm = (const float*)d_in[5];
    const float* Wph   = (const float*)d_in[6];
    const float* bph   = (const float*)d_in[7];
    const float* Wpp   = (const float*)d_in[8];
    const float* bpp   = (const float*)d_in[9];
    const float* Woh   = (const float*)d_in[10];
    const float* boh   = (const float*)d_in[11];
    const float* Wop   = (const float*)d_in[12];
    const float* bop   = (const float*)d_in[13];
    const float* gamma = (const float*)d_in[14];
    const float* beta  = (const float*)d_in[15];
    float* out = (float*)d_out;

    k_init<<<(N + 255) / 256, 256>>>();
    k_hist<<<(E + 255) / 256, 256>>>(dst);
    k_scan<<<1, 1024>>>();
    k_scatter<<<(E + 255) / 256, 256>>>(dst, src);
    k_nodepre<<<(N + 127) / 128, 256>>>(h, p, Wph, Wpp);
    k_edgeE<<<E / 128, 256>>>(e, Wph, bph, Wpp, bpp);
    k_agg<<<(N * 32 + 255) / 256, 256>>>();
    k_nodegemm<<<(N + 127) / 128, 256>>>(h, p, snorm, Woh, boh, Wop, bop, out);
    k_bnstats<<<(N + 127) / 128, 256>>>(out);
    k_bnapply<<<(N * 64 + 255) / 256, 256>>>(out, gamma, beta);
}

// round 4
// speedup vs baseline: 2.6233x; 1.0706x over previous
#include <cuda_runtime.h>
#include <math.h>

namespace {

constexpr int N = 50000;
constexpr int E = 800000;
constexpr float AVG_D_LOG = 2.8332f;
constexpr float EPS_STD = 1e-5f;
constexpr float EPS_BN = 1e-5f;
constexpr float FLT_BIG = 3.402823466e+38f;
constexpr int PITCH = 130;     // k-major Xs pitch for 128-wide tiles

typedef unsigned long long ull;

__device__ __forceinline__ ull fma2(ull a, ull b, ull c) {
    ull d;
    asm("fma.rn.f32x2 %0,%1,%2,%3;" : "=l"(d) : "l"(a), "l"(b), "l"(c));
    return d;
}
__device__ __forceinline__ ull pack2(float x, float y) {
    ull d;
    asm("mov.b64 %0,{%1,%2};" : "=l"(d) : "f"(x), "f"(y));
    return d;
}
__device__ __forceinline__ float2 unpack2(ull v) {
    float2 r;
    asm("mov.b64 {%0,%1},%2;" : "=f"(r.x), "=f"(r.y) : "l"(v));
    return r;
}

// ---- scratch (device globals: allocation-free contract) ----
__device__ int g_deg[N];
__device__ int g_offs[N + 1];
__device__ int g_cursor[N];
__device__ int g_perm[E];
__device__ int g_srcs[E];                                // src id at sorted position
__device__ __align__(16) float g_Ah[(size_t)N * 64];     // h @ W1
__device__ __align__(16) float g_Bh[(size_t)N * 64];     // h @ W2
__device__ __align__(16) float g_Ap[(size_t)N * 64];     // p @ P1
__device__ __align__(16) float g_Bp[(size_t)N * 64];     // p @ P2
__device__ __align__(16) float g_ceh[(size_t)E * 64];    // e @ W3 + b  (sorted order)
__device__ __align__(16) float g_cep[(size_t)E * 64];
__device__ __align__(16) float g_aggh[(size_t)N * 256];  // [mean|max|min|std]
__device__ __align__(16) float g_aggp[(size_t)N * 256];
__device__ float g_amp[N];
__device__ float g_att[N];
__device__ float g_bnsum[64];
__device__ float g_bnsq[64];

// ---------------- init ----------------
__global__ void k_init() {
    int i = blockIdx.x * blockDim.x + threadIdx.x;
    if (i < N) g_deg[i] = 0;
    if (i < 64) { g_bnsum[i] = 0.f; g_bnsq[i] = 0.f; }
}

// ---------------- degree histogram ----------------
__global__ void k_hist(const int* __restrict__ dst) {
    int e = blockIdx.x * blockDim.x + threadIdx.x;
    if (e < E) atomicAdd(&g_deg[dst[e]], 1);
}

// ---------------- exclusive scan (single block) ----------------
__global__ void k_scan() {
    __shared__ int s[1024];
    int t = threadIdx.x;
    int carry = 0;
    for (int base = 0; base < N; base += 1024) {
        int v = (base + t < N) ? g_deg[base + t] : 0;
        s[t] = v;
        __syncthreads();
        for (int off = 1; off < 1024; off <<= 1) {
            int add = (t >= off) ? s[t - off] : 0;
            __syncthreads();
            s[t] += add;
            __syncthreads();
        }
        int incl = s[t];
        if (base + t < N) {
            int ex = carry + incl - v;
            g_offs[base + t] = ex;
            g_cursor[base + t] = ex;
        }
        carry += s[1023];
        __syncthreads();
    }
    if (t == 0) g_offs[N] = carry;
}

// ---------------- scatter: counting sort by dst ----------------
__global__ void k_scatter(const int* __restrict__ dst, const int* __restrict__ src) {
    int e = blockIdx.x * blockDim.x + threadIdx.x;
    if (e < E) {
        int pos = atomicAdd(&g_cursor[dst[e]], 1);
        g_perm[pos] = e;
        g_srcs[pos] = src[e];
    }
}

// ---------------- node pre-GEMMs: Ah=h@W1, Bh=h@W2, Ap=p@P1, Bp=p@P2 --------------
__global__ void __launch_bounds__(256) k_nodepre(
    const float* __restrict__ h, const float* __restrict__ p,
    const float* __restrict__ Wh, const float* __restrict__ Wp)
{
    __shared__ __align__(16) float Xs[32 * PITCH];
    __shared__ __align__(16) float Ws[32 * 128];

    int tid = threadIdx.x;
    int base = blockIdx.x * 128;

    int tx = tid & 15;
    int te = tid >> 4;
    int le = tid & 127;
    int lh = (tid >> 7) * 16;
    int wkk = tid >> 3;          // 0..31
    int woc = (tid & 7) * 16;    // 0,16,...,112

    int nl = base + le;
    bool okl = nl < N;

    ull acca[4][4], accb[4][4];

    // ===== h phase: Ah (W rows 0..127), Bh (W rows 128..255), K=128 =====
#pragma unroll
    for (int i = 0; i < 4; i++)
#pragma unroll
        for (int j = 0; j < 4; j++) { acca[i][j] = 0ull; accb[i][j] = 0ull; }

    for (int t = 0; t < 4; t++) {
        int k0 = t * 32;
        const float* rowp = h + (size_t)nl * 128 + k0;
#pragma unroll
        for (int q = 0; q < 4; q++) {
            float4 a = okl ? *(const float4*)(rowp + lh + q * 4)
                           : make_float4(0.f, 0.f, 0.f, 0.f);
            Xs[(lh + q * 4 + 0) * PITCH + le] = a.x;
            Xs[(lh + q * 4 + 1) * PITCH + le] = a.y;
            Xs[(lh + q * 4 + 2) * PITCH + le] = a.z;
            Xs[(lh + q * 4 + 3) * PITCH + le] = a.w;
        }
        {
            const float* wr = (woc < 64) ? (Wh + (size_t)(k0 + wkk) * 64 + woc)
                                         : (Wh + (size_t)(128 + k0 + wkk) * 64 + (woc - 64));
#pragma unroll
            for (int q = 0; q < 4; q++)
                *(float4*)&Ws[wkk * 128 + woc + q * 4] = *(const float4*)(wr + q * 4);
        }
        __syncthreads();
#pragma unroll 16
        for (int kk = 0; kk < 32; kk++) {
            float4 wa = *(const float4*)&Ws[kk * 128 + tx * 4];
            float4 wb = *(const float4*)&Ws[kk * 128 + 64 + tx * 4];
            ull a0 = pack2(wa.x, wa.x), a1 = pack2(wa.y, wa.y);
            ull a2 = pack2(wa.z, wa.z), a3 = pack2(wa.w, wa.w);
            ull b0 = pack2(wb.x, wb.x), b1 = pack2(wb.y, wb.y);
            ull b2 = pack2(wb.z, wb.z), b3 = pack2(wb.w, wb.w);
            const ull* xp = (const ull*)&Xs[kk * PITCH + te * 8];
#pragma unroll
            for (int i = 0; i < 4; i++) {
                ull x = xp[i];
                acca[i][0] = fma2(x, a0, acca[i][0]);
                acca[i][1] = fma2(x, a1, acca[i][1]);
                acca[i][2] = fma2(x, a2, acca[i][2]);
                acca[i][3] = fma2(x, a3, acca[i][3]);
                accb[i][0] = fma2(x, b0, accb[i][0]);
                accb[i][1] = fma2(x, b1, accb[i][1]);
                accb[i][2] = fma2(x, b2, accb[i][2]);
                accb[i][3] = fma2(x, b3, accb[i][3]);
            }
        }
        __syncthreads();
    }
#pragma unroll
    for (int i = 0; i < 4; i++) {
        float2 a0 = unpack2(acca[i][0]), a1 = unpack2(acca[i][1]);
        float2 a2 = unpack2(acca[i][2]), a3 = unpack2(acca[i][3]);
        float2 b0 = unpack2(accb[i][0]), b1 = unpack2(accb[i][1]);
        float2 b2 = unpack2(accb[i][2]), b3 = unpack2(accb[i][3]);
        int n0 = base + te * 8 + 2 * i;
        if (n0 < N) {
            *(float4*)&g_Ah[(size_t)n0 * 64 + tx * 4] = make_float4(a0.x, a1.x, a2.x, a3.x);
            *(float4*)&g_Bh[(size_t)n0 * 64 + tx * 4] = make_float4(b0.x, b1.x, b2.x, b3.x);
        }
        if (n0 + 1 < N) {
            *(float4*)&g_Ah[(size_t)(n0 + 1) * 64 + tx * 4] = make_float4(a0.y, a1.y, a2.y, a3.y);
            *(float4*)&g_Bh[(size_t)(n0 + 1) * 64 + tx * 4] = make_float4(b0.y, b1.y, b2.y, b3.y);
        }
    }

    // ===== p phase: Ap (P rows 0..63), Bp (P rows 64..127), K=64 =====
#pragma unroll
    for (int i = 0; i < 4; i++)
#pragma unroll
        for (int j = 0; j < 4; j++) { acca[i][j] = 0ull; accb[i][j] = 0ull; }

    for (int t = 0; t < 2; t++) {
        int k0 = t * 32;
        const float* rowp = p + (size_t)nl * 64 + k0;
#pragma unroll
        for (int q = 0; q < 4; q++) {
            float4 a = okl ? *(const float4*)(rowp + lh + q * 4)
                           : make_float4(0.f, 0.f, 0.f, 0.f);
            Xs[(lh + q * 4 + 0) * PITCH + le] = a.x;
            Xs[(lh + q * 4 + 1) * PITCH + le] = a.y;
            Xs[(lh + q * 4 + 2) * PITCH + le] = a.z;
            Xs[(lh + q * 4 + 3) * PITCH + le] = a.w;
        }
        {
            const float* wr = (woc < 64) ? (Wp + (size_t)(k0 + wkk) * 64 + woc)
                                         : (Wp + (size_t)(64 + k0 + wkk) * 64 + (woc - 64));
#pragma unroll
            for (int q = 0; q < 4; q++)
                *(float4*)&Ws[wkk * 128 + woc + q * 4] = *(const float4*)(wr + q * 4);
        }
        __syncthreads();
#pragma unroll 16
        for (int kk = 0; kk < 32; kk++) {
            float4 wa = *(const float4*)&Ws[kk * 128 + tx * 4];
            float4 wb = *(const float4*)&Ws[kk * 128 + 64 + tx * 4];
            ull a0 = pack2(wa.x, wa.x), a1 = pack2(wa.y, wa.y);
            ull a2 = pack2(wa.z, wa.z), a3 = pack2(wa.w, wa.w);
            ull b0 = pack2(wb.x, wb.x), b1 = pack2(wb.y, wb.y);
            ull b2 = pack2(wb.z, wb.z), b3 = pack2(wb.w, wb.w);
            const ull* xp = (const ull*)&Xs[kk * PITCH + te * 8];
#pragma unroll
            for (int i = 0; i < 4; i++) {
                ull x = xp[i];
                acca[i][0] = fma2(x, a0, acca[i][0]);
                acca[i][1] = fma2(x, a1, acca[i][1]);
                acca[i][2] = fma2(x, a2, acca[i][2]);
                acca[i][3] = fma2(x, a3, acca[i][3]);
                accb[i][0] = fma2(x, b0, accb[i][0]);
                accb[i][1] = fma2(x, b1, accb[i][1]);
                accb[i][2] = fma2(x, b2, accb[i][2]);
                accb[i][3] = fma2(x, b3, accb[i][3]);
            }
        }
        __syncthreads();
    }
#pragma unroll
    for (int i = 0; i < 4; i++) {
        float2 a0 = unpack2(acca[i][0]), a1 = unpack2(acca[i][1]);
        float2 a2 = unpack2(acca[i][2]), a3 = unpack2(acca[i][3]);
        float2 b0 = unpack2(accb[i][0]), b1 = unpack2(accb[i][1]);
        float2 b2 = unpack2(accb[i][2]), b3 = unpack2(accb[i][3]);
        int n0 = base + te * 8 + 2 * i;
        if (n0 < N) {
            *(float4*)&g_Ap[(size_t)n0 * 64 + tx * 4] = make_float4(a0.x, a1.x, a2.x, a3.x);
            *(float4*)&g_Bp[(size_t)n0 * 64 + tx * 4] = make_float4(b0.x, b1.x, b2.x, b3.x);
        }
        if (n0 + 1 < N) {
            *(float4*)&g_Ap[(size_t)(n0 + 1) * 64 + tx * 4] = make_float4(a0.y, a1.y, a2.y, a3.y);
            *(float4*)&g_Bp[(size_t)(n0 + 1) * 64 + tx * 4] = make_float4(b0.y, b1.y, b2.y, b3.y);
        }
    }
}

// ---------------- edge-feature GEMM: Ceh = e@W3 + bh, Cep = e@P3 + bp (sorted) -------
__global__ void __launch_bounds__(256) k_edgeE(
    const float* __restrict__ ef,
    const float* __restrict__ Wh, const float* __restrict__ bh,
    const float* __restrict__ Wp, const float* __restrict__ bp)
{
    __shared__ __align__(16) float Xs[32 * PITCH];
    __shared__ __align__(16) float Ws[32 * 128];
    __shared__ int s_eid[128];

    int tid = threadIdx.x;
    int base = blockIdx.x * 128;

    for (int j = tid; j < 128; j += 256) s_eid[j] = g_perm[base + j];

    int tx = tid & 15;
    int te = tid >> 4;
    int le = tid & 127;
    int lh = (tid >> 7) * 16;
    int wkk = tid >> 3;
    int woc = (tid & 7) * 16;

    {
        const float* wr = (woc < 64) ? (Wh + (size_t)(256 + wkk) * 64 + woc)
                                     : (Wp + (size_t)(128 + wkk) * 64 + (woc - 64));
#pragma unroll
        for (int q = 0; q < 4; q++)
            *(float4*)&Ws[wkk * 128 + woc + q * 4] = *(const float4*)(wr + q * 4);
    }
    __syncthreads();
    {
        const float* rowp = ef + (size_t)s_eid[le] * 32;
#pragma unroll
        for (int q = 0; q < 4; q++) {
            float4 a = *(const float4*)(rowp + lh + q * 4);
            Xs[(lh + q * 4 + 0) * PITCH + le] = a.x;
            Xs[(lh + q * 4 + 1) * PITCH + le] = a.y;
            Xs[(lh + q * 4 + 2) * PITCH + le] = a.z;
            Xs[(lh + q * 4 + 3) * PITCH + le] = a.w;
        }
    }
    __syncthreads();

    ull acca[4][4], accb[4][4];
#pragma unroll
    for (int i = 0; i < 4; i++)
#pragma unroll
        for (int j = 0; j < 4; j++) { acca[i][j] = 0ull; accb[i][j] = 0ull; }

#pragma unroll 16
    for (int kk = 0; kk < 32; kk++) {
        float4 wa = *(const float4*)&Ws[kk * 128 + tx * 4];
        float4 wb = *(const float4*)&Ws[kk * 128 + 64 + tx * 4];
        ull a0 = pack2(wa.x, wa.x), a1 = pack2(wa.y, wa.y);
        ull a2 = pack2(wa.z, wa.z), a3 = pack2(wa.w, wa.w);
        ull b0 = pack2(wb.x, wb.x), b1 = pack2(wb.y, wb.y);
        ull b2 = pack2(wb.z, wb.z), b3 = pack2(wb.w, wb.w);
        const ull* xp = (const ull*)&Xs[kk * PITCH + te * 8];
#pragma unroll
        for (int i = 0; i < 4; i++) {
            ull x = xp[i];
            acca[i][0] = fma2(x, a0, acca[i][0]);
            acca[i][1] = fma2(x, a1, acca[i][1]);
            acca[i][2] = fma2(x, a2, acca[i][2]);
            acca[i][3] = fma2(x, a3, acca[i][3]);
            accb[i][0] = fma2(x, b0, accb[i][0]);
            accb[i][1] = fma2(x, b1, accb[i][1]);
            accb[i][2] = fma2(x, b2, accb[i][2]);
            accb[i][3] = fma2(x, b3, accb[i][3]);
        }
    }

    float4 biash = *(const float4*)&bh[tx * 4];
    float4 biasp = *(const float4*)&bp[tx * 4];
#pragma unroll
    for (int i = 0; i < 4; i++) {
        float2 a0 = unpack2(acca[i][0]), a1 = unpack2(acca[i][1]);
        float2 a2 = unpack2(acca[i][2]), a3 = unpack2(acca[i][3]);
        float2 b0 = unpack2(accb[i][0]), b1 = unpack2(accb[i][1]);
        float2 b2 = unpack2(accb[i][2]), b3 = unpack2(accb[i][3]);
        int pos = base + te * 8 + 2 * i;
        *(float4*)&g_ceh[(size_t)pos * 64 + tx * 4] =
            make_float4(a0.x + biash.x, a1.x + biash.y, a2.x + biash.z, a3.x + biash.w);
        *(float4*)&g_ceh[(size_t)(pos + 1) * 64 + tx * 4] =
            make_float4(a0.y + biash.x, a1.y + biash.y, a2.y + biash.z, a3.y + biash.w);
        *(float4*)&g_cep[(size_t)pos * 64 + tx * 4] =
            make_float4(b0.x + biasp.x, b1.x + biasp.y, b2.x + biasp.z, b3.x + biasp.w);
        *(float4*)&g_cep[(size_t)(pos + 1) * 64 + tx * 4] =
            make_float4(b0.y + biasp.x, b1.y + biasp.y, b2.y + biasp.z, b3.y + biasp.w);
    }
}

// ---------------- fused message + PNA aggregation (warp per node) -------------
// Writes FACTORED agg: [mean|max|min|std] (256 floats per side) + amp/att per node.
__global__ void k_agg() {
    int warp = (blockIdx.x * blockDim.x + threadIdx.x) >> 5;
    int l = threadIdx.x & 31;
    if (warp >= N) return;
    int n = warp;
    int s0 = g_offs[n];
    int s1 = g_offs[n + 1];
    int d = s1 - s0;

    float bh0 = g_Bh[(size_t)n * 64 + l];
    float bh1 = g_Bh[(size_t)n * 64 + l + 32];
    float bp0 = g_Bp[(size_t)n * 64 + l];
    float bp1 = g_Bp[(size_t)n * 64 + l + 32];

    float sm[4] = {0.f, 0.f, 0.f, 0.f};
    float sq[4] = {0.f, 0.f, 0.f, 0.f};
    float mx[4] = {-FLT_BIG, -FLT_BIG, -FLT_BIG, -FLT_BIG};
    float mn[4] = {FLT_BIG, FLT_BIG, FLT_BIG, FLT_BIG};

    for (int i = s0; i < s1; i++) {
        int s = g_srcs[i];
        const float* ah = g_Ah + (size_t)s * 64;
        const float* ap = g_Ap + (size_t)s * 64;
        const float* ch = g_ceh + (size_t)i * 64;
        const float* cp = g_cep + (size_t)i * 64;
        float v0 = ch[l]      + ah[l]      + bh0;
        float v1 = ch[l + 32] + ah[l + 32] + bh1;
        float v2 = cp[l]      + ap[l]      + bp0;
        float v3 = cp[l + 32] + ap[l + 32] + bp1;
        sm[0] += v0; sq[0] += v0 * v0; mx[0] = fmaxf(mx[0], v0); mn[0] = fminf(mn[0], v0);
        sm[1] += v1; sq[1] += v1 * v1; mx[1] = fmaxf(mx[1], v1); mn[1] = fminf(mn[1], v1);
        sm[2] += v2; sq[2] += v2 * v2; mx[2] = fmaxf(mx[2], v2); mn[2] = fminf(mn[2], v2);
        sm[3] += v3; sq[3] += v3 * v3; mx[3] = fmaxf(mx[3], v3); mn[3] = fminf(mn[3], v3);
    }

    float degc = fmaxf((float)d, 1.f);
    float inv = 1.f / degc;
    bool has = d > 0;
    float logd = has ? logf((float)d + 1.f) : 1.f;
    float amp = logd / AVG_D_LOG;
    float att = AVG_D_LOG / logd;
    if (l == 0) { g_amp[n] = amp; g_att[n] = att; }

    float* outh = g_aggh + (size_t)n * 256;
    float* outp = g_aggp + (size_t)n * 256;

#pragma unroll
    for (int c = 0; c < 4; c++) {
        float mean = sm[c] * inv;
        float var = fmaxf(sq[c] * inv - mean * mean, 0.f);
        float sd = sqrtf(var + EPS_STD);
        float MX = has ? mx[c] : 0.f;
        float MN = has ? mn[c] : 0.f;
        float* o = (c < 2) ? outh : outp;
        int f = l + ((c & 1) ? 32 : 0);
        o[f] = mean; o[64 + f] = MX; o[128 + f] = MN; o[192 + f] = sd;
    }
}

// ---------------- node GEMMs with factored scalers (3 accumulator rails) ----------
// 64 nodes x 64 outs per block; 256 threads = 32 tx (2 outs) x 8 te (8 nodes).
__global__ void __launch_bounds__(256) k_nodegemm(
    const float* __restrict__ h, const float* __restrict__ p,
    const float* __restrict__ snorm,
    const float* __restrict__ Woh, const float* __restrict__ boh,
    const float* __restrict__ Wop, const float* __restrict__ bop,
    float* __restrict__ out)
{
    __shared__ __align__(16) float Xs[32 * 64];
    __shared__ __align__(16) float Ws[3 * 32 * 64];   // rails I, A, T

    int tid = threadIdx.x;
    int base = blockIdx.x * 64;

    int tx = tid & 31;          // outs 2tx, 2tx+1
    int te = tid >> 5;          // nodes te*8 .. te*8+7
    int le = tid & 63;          // loader node
    int lh = (tid >> 6) * 8;    // loader k offset 0/8/16/24
    int wkk = tid >> 3;         // W loader row 0..31
    int woc = (tid & 7) * 8;    // W loader col

    int nl = base + le;
    bool okl = nl < N;

    ull accI[4][2], accA[4][2], accT[4][2];

    // =================== phase H: base K=128 (4 tiles) + agg K=256 (8 tiles) =========
#pragma unroll
    for (int i = 0; i < 4; i++)
#pragma unroll
        for (int j = 0; j < 2; j++) { accI[i][j] = 0ull; accA[i][j] = 0ull; accT[i][j] = 0ull; }

    for (int t = 0; t < 12; t++) {
        int k0 = t * 32;
        bool isAgg = (t >= 4);
        const float* rowp = isAgg ? (g_aggh + (size_t)nl * 256 + (k0 - 128))
                                  : (h + (size_t)nl * 128 + k0);
#pragma unroll
        for (int q = 0; q < 2; q++) {
            float4 a = okl ? *(const float4*)(rowp + lh + q * 4)
                           : make_float4(0.f, 0.f, 0.f, 0.f);
            Xs[(lh + q * 4 + 0) * 64 + le] = a.x;
            Xs[(lh + q * 4 + 1) * 64 + le] = a.y;
            Xs[(lh + q * 4 + 2) * 64 + le] = a.z;
            Xs[(lh + q * 4 + 3) * 64 + le] = a.w;
        }
        if (isAgg) {
            int aggk = k0 - 128;
            const float* wI = Woh + (size_t)(128 + aggk + wkk) * 64 + woc;
            const float* wA = Woh + (size_t)(384 + aggk + wkk) * 64 + woc;
            const float* wT = Woh + (size_t)(640 + aggk + wkk) * 64 + woc;
            *(float4*)&Ws[wkk * 64 + woc]              = *(const float4*)(wI);
            *(float4*)&Ws[wkk * 64 + woc + 4]          = *(const float4*)(wI + 4);
            *(float4*)&Ws[2048 + wkk * 64 + woc]       = *(const float4*)(wA);
            *(float4*)&Ws[2048 + wkk * 64 + woc + 4]   = *(const float4*)(wA + 4);
            *(float4*)&Ws[4096 + wkk * 64 + woc]       = *(const float4*)(wT);
            *(float4*)&Ws[4096 + wkk * 64 + woc + 4]   = *(const float4*)(wT + 4);
        } else {
            const float* wI = Woh + (size_t)(k0 + wkk) * 64 + woc;
            *(float4*)&Ws[wkk * 64 + woc]     = *(const float4*)(wI);
            *(float4*)&Ws[wkk * 64 + woc + 4] = *(const float4*)(wI + 4);
        }
        __syncthreads();
        if (isAgg) {
#pragma unroll 8
            for (int kk = 0; kk < 32; kk++) {
                float2 wi = *(const float2*)&Ws[kk * 64 + tx * 2];
                float2 wa = *(const float2*)&Ws[2048 + kk * 64 + tx * 2];
                float2 wt = *(const float2*)&Ws[4096 + kk * 64 + tx * 2];
                ull i0 = pack2(wi.x, wi.x), i1 = pack2(wi.y, wi.y);
                ull a0 = pack2(wa.x, wa.x), a1 = pack2(wa.y, wa.y);
                ull t0 = pack2(wt.x, wt.x), t1 = pack2(wt.y, wt.y);
                const ull* xp = (const ull*)&Xs[kk * 64 + te * 8];
#pragma unroll
                for (int i = 0; i < 4; i++) {
                    ull x = xp[i];
                    accI[i][0] = fma2(x, i0, accI[i][0]);
                    accI[i][1] = fma2(x, i1, accI[i][1]);
                    accA[i][0] = fma2(x, a0, accA[i][0]);
                    accA[i][1] = fma2(x, a1, accA[i][1]);
                    accT[i][0] = fma2(x, t0, accT[i][0]);
                    accT[i][1] = fma2(x, t1, accT[i][1]);
                }
            }
        } else {
#pragma unroll 8
            for (int kk = 0; kk < 32; kk++) {
                float2 wi = *(const float2*)&Ws[kk * 64 + tx * 2];
                ull i0 = pack2(wi.x, wi.x), i1 = pack2(wi.y, wi.y);
                const ull* xp = (const ull*)&Xs[kk * 64 + te * 8];
#pragma unroll
                for (int i = 0; i < 4; i++) {
                    ull x = xp[i];
                    accI[i][0] = fma2(x, i0, accI[i][0]);
                    accI[i][1] = fma2(x, i1, accI[i][1]);
                }
            }
        }
        __syncthreads();
    }
    {
        float2 bias = *(const float2*)&boh[tx * 2];
#pragma unroll
        for (int i = 0; i < 4; i++) {
            int n0 = base + te * 8 + 2 * i;
            float am0 = (n0 < N) ? g_amp[n0] : 0.f;
            float am1 = (n0 + 1 < N) ? g_amp[n0 + 1] : 0.f;
            float at0 = (n0 < N) ? g_att[n0] : 0.f;
            float at1 = (n0 + 1 < N) ? g_att[n0 + 1] : 0.f;
            ull ampP = pack2(am0, am1), attP = pack2(at0, at1);
            ull y0 = fma2(attP, accT[i][0], fma2(ampP, accA[i][0], accI[i][0]));
            ull y1 = fma2(attP, accT[i][1], fma2(ampP, accA[i][1], accI[i][1]));
            float2 u0 = unpack2(y0), u1 = unpack2(y1);
            if (n0 < N) {
                float sn = snorm[n0];
                *(float2*)&out[(size_t)n0 * 64 + tx * 2] =
                    make_float2((u0.x + bias.x) * sn, (u1.x + bias.y) * sn);
            }
            if (n0 + 1 < N) {
                float sn = snorm[n0 + 1];
                *(float2*)&out[(size_t)(n0 + 1) * 64 + tx * 2] =
                    make_float2((u0.y + bias.x) * sn, (u1.y + bias.y) * sn);
            }
        }
    }

    // =================== phase P: base K=64 (2 tiles) + agg K=256 (8 tiles) ==========
#pragma unroll
    for (int i = 0; i < 4; i++)
#pragma unroll
        for (int j = 0; j < 2; j++) { accI[i][j] = 0ull; accA[i][j] = 0ull; accT[i][j] = 0ull; }

    for (int t = 0; t < 10; t++) {
        int k0 = t * 32;
        bool isAgg = (t >= 2);
        const float* rowp = isAgg ? (g_aggp + (size_t)nl * 256 + (k0 - 64))
                                  : (p + (size_t)nl * 64 + k0);
#pragma unroll
        for (int q = 0; q < 2; q++) {
            float4 a = okl ? *(const float4*)(rowp + lh + q * 4)
                           : make_float4(0.f, 0.f, 0.f, 0.f);
            Xs[(lh + q * 4 + 0) * 64 + le] = a.x;
            Xs[(lh + q * 4 + 1) * 64 + le] = a.y;
            Xs[(lh + q * 4 + 2) * 64 + le] = a.z;
            Xs[(lh + q * 4 + 3) * 64 + le] = a.w;
        }
        if (isAgg) {
            int aggk = k0 - 64;
            const float* wI = Wop + (size_t)(64 + aggk + wkk) * 64 + woc;
            const float* wA = Wop + (size_t)(320 + aggk + wkk) * 64 + woc;
            const float* wT = Wop + (size_t)(576 + aggk + wkk) * 64 + woc;
            *(float4*)&Ws[wkk * 64 + woc]              = *(const float4*)(wI);
            *(float4*)&Ws[wkk * 64 + woc + 4]          = *(const float4*)(wI + 4);
            *(float4*)&Ws[2048 + wkk * 64 + woc]       = *(const float4*)(wA);
            *(float4*)&Ws[2048 + wkk * 64 + woc + 4]   = *(const float4*)(wA + 4);
            *(float4*)&Ws[4096 + wkk * 64 + woc]       = *(const float4*)(wT);
            *(float4*)&Ws[4096 + wkk * 64 + woc + 4]   = *(const float4*)(wT + 4);
        } else {
            const float* wI = Wop + (size_t)(k0 + wkk) * 64 + woc;
            *(float4*)&Ws[wkk * 64 + woc]     = *(const float4*)(wI);
            *(float4*)&Ws[wkk * 64 + woc + 4] = *(const float4*)(wI + 4);
        }
        __syncthreads();
        if (isAgg) {
#pragma unroll 8
            for (int kk = 0; kk < 32; kk++) {
                float2 wi = *(const float2*)&Ws[kk * 64 + tx * 2];
                float2 wa = *(const float2*)&Ws[2048 + kk * 64 + tx * 2];
                float2 wt = *(const float2*)&Ws[4096 + kk * 64 + tx * 2];
                ull i0 = pack2(wi.x, wi.x), i1 = pack2(wi.y, wi.y);
                ull a0 = pack2(wa.x, wa.x), a1 = pack2(wa.y, wa.y);
                ull t0 = pack2(wt.x, wt.x), t1 = pack2(wt.y, wt.y);
                const ull* xp = (const ull*)&Xs[kk * 64 + te * 8];
#pragma unroll
                for (int i = 0; i < 4; i++) {
                    ull x = xp[i];
                    accI[i][0] = fma2(x, i0, accI[i][0]);
                    accI[i][1] = fma2(x, i1, accI[i][1]);
                    accA[i][0] = fma2(x, a0, accA[i][0]);
                    accA[i][1] = fma2(x, a1, accA[i][1]);
                    accT[i][0] = fma2(x, t0, accT[i][0]);
                    accT[i][1] = fma2(x, t1, accT[i][1]);
                }
            }
        } else {
#pragma unroll 8
            for (int kk = 0; kk < 32; kk++) {
                float2 wi = *(const float2*)&Ws[kk * 64 + tx * 2];
                ull i0 = pack2(wi.x, wi.x), i1 = pack2(wi.y, wi.y);
                const ull* xp = (const ull*)&Xs[kk * 64 + te * 8];
#pragma unroll
                for (int i = 0; i < 4; i++) {
                    ull x = xp[i];
                    accI[i][0] = fma2(x, i0, accI[i][0]);
                    accI[i][1] = fma2(x, i1, accI[i][1]);
                }
            }
        }
        __syncthreads();
    }
    {
        float2 bias = *(const float2*)&bop[tx * 2];
        float* outp = out + (size_t)N * 64;
#pragma unroll
        for (int i = 0; i < 4; i++) {
            int n0 = base + te * 8 + 2 * i;
            float am0 = (n0 < N) ? g_amp[n0] : 0.f;
            float am1 = (n0 + 1 < N) ? g_amp[n0 + 1] : 0.f;
            float at0 = (n0 < N) ? g_att[n0] : 0.f;
            float at1 = (n0 + 1 < N) ? g_att[n0 + 1] : 0.f;
            ull ampP = pack2(am0, am1), attP = pack2(at0, at1);
            ull y0 = fma2(attP, accT[i][0], fma2(ampP, accA[i][0], accI[i][0]));
            ull y1 = fma2(attP, accT[i][1], fma2(ampP, accA[i][1], accI[i][1]));
            float2 u0 = unpack2(y0), u1 = unpack2(y1);
            if (n0 < N)
                *(float2*)&outp[(size_t)n0 * 64 + tx * 2] =
                    make_float2(u0.x + bias.x, u1.x + bias.y);
            if (n0 + 1 < N)
                *(float2*)&outp[(size_t)(n0 + 1) * 64 + tx * 2] =
                    make_float2(u0.y + bias.x, u1.y + bias.y);
        }
    }
}

// ---------------- batchnorm stats ----------------
__global__ void k_bnstats(const float* __restrict__ out) {
    __shared__ float ss[4][64];
    __shared__ float sqv[4][64];
    int f = threadIdx.x & 63;
    int rg = threadIdx.x >> 6;
    int r0 = blockIdx.x * 128;
    int rend = r0 + 128;
    if (rend > N) rend = N;
    float s = 0.f, q = 0.f;
    for (int r = r0 + rg; r < rend; r += 4) {
        float x = out[(size_t)r * 64 + f];
        s += x; q += x * x;
    }
    ss[rg][f] = s; sqv[rg][f] = q;
    __syncthreads();
    if (threadIdx.x < 64) {
        float S = ss[0][f] + ss[1][f] + ss[2][f] + ss[3][f];
        float Q = sqv[0][f] + sqv[1][f] + sqv[2][f] + sqv[3][f];
        atomicAdd(&g_bnsum[f], S);
        atomicAdd(&g_bnsq[f], Q);
    }
}

// ---------------- batchnorm apply ----------------
__global__ void k_bnapply(float* __restrict__ out,
                          const float* __restrict__ gamma,
                          const float* __restrict__ beta) {
    int i = blockIdx.x * blockDim.x + threadIdx.x;
    if (i >= N * 64) return;
    int f = i & 63;
    const float invN = 1.f / (float)N;
    float mu = g_bnsum[f] * invN;
    float var = g_bnsq[f] * invN - mu * mu;
    float x = out[i];
    out[i] = (x - mu) * rsqrtf(var + EPS_BN) * gamma[f] + beta[f];
}

} // namespace

extern "C" void kernel_launch(void* const* d_in, const int* in_sizes, int n_in,
                              void* d_out, int out_size) {
    const float* h     = (const float*)d_in[0];
    const float* p     = (const float*)d_in[1];
    const float* e     = (const float*)d_in[2];
    const int*   src   = (const int*)d_in[3];
    const int*   dst   = (const int*)d_in[4];
    const float* snorm = (const float*)d_in[5];
    const float* Wph   = (const float*)d_in[6];
    const float* bph   = (const float*)d_in[7];
    const float* Wpp   = (const float*)d_in[8];
    const float* bpp   = (const float*)d_in[9];
    const float* Woh   = (const float*)d_in[10];
    const float* boh   = (const float*)d_in[11];
    const float* Wop   = (const float*)d_in[12];
    const float* bop   = (const float*)d_in[13];
    const float* gamma = (const float*)d_in[14];
    const float* beta  = (const float*)d_in[15];
    float* out = (float*)d_out;

    k_init<<<(N + 255) / 256, 256>>>();
    k_hist<<<(E + 255) / 256, 256>>>(dst);
    k_scan<<<1, 1024>>>();
    k_scatter<<<(E + 255) / 256, 256>>>(dst, src);
    k_nodepre<<<(N + 127) / 128, 256>>>(h, p, Wph, Wpp);
    k_edgeE<<<E / 128, 256>>>(e, Wph, bph, Wpp, bpp);
    k_agg<<<(N * 32 + 255) / 256, 256>>>();
    k_nodegemm<<<(N + 63) / 64, 256>>>(h, p, snorm, Woh, boh, Wop, bop, out);
    k_bnstats<<<(N + 127) / 128, 256>>>(out);
    k_bnapply<<<(N * 64 + 255) / 256, 256>>>(out, gamma, beta);
}